// round 4
// baseline (speedup 1.0000x reference)
#include <cuda_runtime.h>
#include <cuda_bf16.h>
#include <cstdint>
#include <cstring>

// Problem constants
#define T_PADDED 65656
#define T_OUT    65536
#define NROWS    768
#define CCH      384
#define NB       168
#define HOP      392
#define OVL      120

#define SWZ(x) ((x) ^ (((x) >> 3) & 0x70))

// ---------------- device globals (allocation-free rule) ----------------
__device__ float g_h[512];
__device__ uint4 g_Bc[4 * 7 * 2 * 1024];   // circulant tiles [jt][kc][plane], 16KB planes
__device__ uint4 g_Bw[3 * 6 * 2 * 1024];   // W tiles [dt][kc][plane]
__device__ float g_C[(size_t)NB * 512 * NROWS]; // [b][j][r]

// ---------------- helpers ----------------
__device__ __forceinline__ uint32_t smem_u32(const void* p) {
    uint32_t a;
    asm("{ .reg .u64 t; cvta.to.shared.u64 t, %1; cvt.u32.u64 %0, t; }" : "=r"(a) : "l"(p));
    return a;
}
__device__ __forceinline__ void ldm4(uint32_t addr, uint32_t* r) {
    asm volatile("ldmatrix.sync.aligned.m8n8.x4.shared.b16 {%0,%1,%2,%3}, [%4];"
                 : "=r"(r[0]), "=r"(r[1]), "=r"(r[2]), "=r"(r[3]) : "r"(addr));
}
__device__ __forceinline__ void mma16816(float* c, const uint32_t* a, const uint32_t* b) {
    asm volatile("mma.sync.aligned.m16n8k16.row.col.f32.bf16.bf16.f32 "
                 "{%0,%1,%2,%3},{%4,%5,%6,%7},{%8,%9},{%0,%1,%2,%3};"
                 : "+f"(c[0]), "+f"(c[1]), "+f"(c[2]), "+f"(c[3])
                 : "r"(a[0]), "r"(a[1]), "r"(a[2]), "r"(a[3]), "r"(b[0]), "r"(b[1]));
}
#define CP16(s, g)  asm volatile("cp.async.cg.shared.global [%0], [%1], 16;" :: "r"(s), "l"(g))
#define CP_COMMIT() asm volatile("cp.async.commit_group;" ::: "memory")
#define CP_WAIT1()  asm volatile("cp.async.wait_group 1;" ::: "memory")

__device__ __forceinline__ unsigned pkb(__nv_bfloat16 a, __nv_bfloat16 b) {
    unsigned short ua, ub;
    memcpy(&ua, &a, 2); memcpy(&ub, &b, 2);
    return ((unsigned)ub << 16) | ua;
}
__device__ __forceinline__ void split4(float4 v, uint2& hi, uint2& lo) {
    __nv_bfloat16 h0 = __float2bfloat16(v.x), h1 = __float2bfloat16(v.y),
                  h2 = __float2bfloat16(v.z), h3 = __float2bfloat16(v.w);
    __nv_bfloat16 l0 = __float2bfloat16(v.x - __bfloat162float(h0));
    __nv_bfloat16 l1 = __float2bfloat16(v.y - __bfloat162float(h1));
    __nv_bfloat16 l2 = __float2bfloat16(v.z - __bfloat162float(h2));
    __nv_bfloat16 l3 = __float2bfloat16(v.w - __bfloat162float(h3));
    hi = make_uint2(pkb(h0, h1), pkb(h2, h3));
    lo = make_uint2(pkb(l0, l1), pkb(l2, l3));
}

// ---------------- kernel 1: h = irfft(H, 512) ----------------
__global__ void k_irfft(const float* __restrict__ H) {
    int j = threadIdx.x;
    float acc = H[0] + ((j & 1) ? -H[256] : H[256]);
    const float w = 6.283185307179586476f / 512.0f;
    for (int m = 1; m < 256; m++) {
        int ph = (m * j) & 511;
        acc += 2.0f * H[m] * cosf(w * (float)ph);
    }
    g_h[j] = acc * (1.0f / 512.0f);
}

// ---------------- kernel 1b: circulant tiles [j][k] bf16 hi/lo, SW128 ----------------
__global__ void k_build_Bc() {
    __shared__ float sh[512];
    int jt = blockIdx.x, kc = blockIdx.y;
    int tid = threadIdx.x;
    sh[tid] = g_h[tid]; sh[tid + 256] = g_h[tid + 256];
    __syncthreads();
    char* hiB = (char*)g_Bc + (size_t)((jt * 7 + kc) * 2 + 0) * 16384;
    char* loB = (char*)g_Bc + (size_t)((jt * 7 + kc) * 2 + 1) * 16384;
    for (int e = tid; e < 8192; e += 256) {
        int jl = e >> 6, kl = e & 63;
        int k = kc * 64 + kl;
        float v = (k < HOP) ? sh[(jt * 128 + jl - k) & 511] : 0.0f;
        __nv_bfloat16 h = __float2bfloat16(v);
        __nv_bfloat16 l = __float2bfloat16(v - __bfloat162float(h));
        int off = SWZ(jl * 128 + kl * 2);
        *(__nv_bfloat16*)(hiB + off) = h;
        *(__nv_bfloat16*)(loB + off) = l;
    }
}

// ---------------- kernel 1c: W tiles [d][c] = std[c]*vt[c][d], bf16 hi/lo, SW128 ----------------
__global__ void k_build_W(const float* __restrict__ vt, const float* __restrict__ sstd) {
    int dt = blockIdx.x, kc = blockIdx.y;
    int tid = threadIdx.x;
    char* hiB = (char*)g_Bw + (size_t)((dt * 6 + kc) * 2 + 0) * 16384;
    char* loB = (char*)g_Bw + (size_t)((dt * 6 + kc) * 2 + 1) * 16384;
    for (int e = tid; e < 8192; e += 256) {
        int kl = e >> 7, dl = e & 127;
        int c = kc * 64 + kl, d = dt * 128 + dl;
        float v = sstd[c] * vt[c * CCH + d];
        __nv_bfloat16 h = __float2bfloat16(v);
        __nv_bfloat16 l = __float2bfloat16(v - __bfloat162float(h));
        int off = SWZ(dl * 128 + kl * 2);
        *(__nv_bfloat16*)(hiB + off) = h;
        *(__nv_bfloat16*)(loB + off) = l;
    }
}

// ============================================================================
// Warp-MMA engine (unchanged from R3): stage s at s*65536:
//   m-side hi @+0, lo @+16384; n-side hi @+32768, lo @+49152.
// 8 warps: wm = wid>>2 (2) x wn = wid&3 (4); warp tile 64m x 32n.
// ============================================================================
__device__ __forceinline__ void gemm_compute(uint32_t sb, int s, int wm, int wn,
                                             int lane, float acc[4][4][4]) {
    const uint32_t sx = (lane & 7) << 4;
    const int kA_l = (lane & 16) >> 1;
    const int kB_l = lane & 8;
    const int mrow = lane & 15;
    const int nrow = (lane & 7) + ((lane & 16) >> 1);
    const uint32_t aBase = sb + s * 65536 + (wm * 64 + mrow) * 128;
    const uint32_t bBase = sb + s * 65536 + 32768 + (wn * 32 + nrow) * 128;

#pragma unroll
    for (int ks = 0; ks < 4; ks++) {
        const uint32_t ka = ((uint32_t)(ks * 16 + kA_l) * 2) ^ sx;
        const uint32_t kb = ((uint32_t)(ks * 16 + kB_l) * 2) ^ sx;
        uint32_t bh[4][2], bl[4][2];
#pragma unroll
        for (int p = 0; p < 2; p++) {
            uint32_t r[4];
            ldm4(bBase + p * 2048 + kb, r);
            bh[2 * p][0] = r[0]; bh[2 * p][1] = r[1];
            bh[2 * p + 1][0] = r[2]; bh[2 * p + 1][1] = r[3];
            ldm4(bBase + 16384 + p * 2048 + kb, r);
            bl[2 * p][0] = r[0]; bl[2 * p][1] = r[1];
            bl[2 * p + 1][0] = r[2]; bl[2 * p + 1][1] = r[3];
        }
#pragma unroll
        for (int mf = 0; mf < 4; mf++) {
            uint32_t ah[4], al[4];
            ldm4(aBase + mf * 2048 + ka, ah);
            ldm4(aBase + 16384 + mf * 2048 + ka, al);
#pragma unroll
            for (int nf = 0; nf < 4; nf++) {
                mma16816(acc[mf][nf], ah, bh[nf]);
                mma16816(acc[mf][nf], ah, bl[nf]);
                mma16816(acc[mf][nf], al, bh[nf]);
            }
        }
    }
}

// ---------------- kernel 2: conv GEMM ----------------
// D[j][r] = sum_k circ[j,k] * noise[r, b*HOP + k]; m=j (A=circulant, cp.async),
// n = col' = b*768+r (B=noise, LDG+split). Output g_C[b][j][r].
__global__ __launch_bounds__(256) void k_conv_mma(const float* __restrict__ noise) {
    extern __shared__ char smem[];
    const uint32_t sb = smem_u32(smem);
    const int tid = threadIdx.x, lane = tid & 31, wid = tid >> 5;
    const int wm = wid >> 2, wn = wid & 3;
    const int b  = blockIdx.x / 6;
    const int r0 = (blockIdx.x % 6) * 128;
    const int jt = blockIdx.y;
    const int kmax = (T_PADDED - b * HOP < HOP) ? (T_PADDED - b * HOP) : HOP;

    const int arow = tid >> 4;
    const int aq = tid & 15;
    const int arx = (arow & 7) << 4;
    const float* nbase = noise + (size_t)(r0 + arow) * T_PADDED + b * HOP;

    float acc[4][4][4];
#pragma unroll
    for (int i = 0; i < 4; i++)
#pragma unroll
        for (int j = 0; j < 4; j++)
#pragma unroll
            for (int q = 0; q < 4; q++) acc[i][j][q] = 0.0f;

    float4 pf[8];

#define CONV_LDG(cc) do { \
    int kk = (cc) * 64 + aq * 4; \
    bool kin = kk < kmax; \
    _Pragma("unroll") \
    for (int p = 0; p < 8; p++) \
        pf[p] = kin ? *(const float4*)(nbase + p * 16 * T_PADDED + kk) \
                    : make_float4(0.f, 0.f, 0.f, 0.f); \
} while (0)
#define CONV_STS(s) do { \
    char* bhi = smem + (s) * 65536 + 32768; \
    char* blo = bhi + 16384; \
    _Pragma("unroll") \
    for (int p = 0; p < 8; p++) { \
        uint2 hi, lo; split4(pf[p], hi, lo); \
        int off = (arow + p * 16) * 128 + ((aq * 8) ^ arx); \
        *(uint2*)(bhi + off) = hi; \
        *(uint2*)(blo + off) = lo; \
    } \
} while (0)
#define CONV_CPA(cc, s) do { \
    const char* src = (const char*)(g_Bc + (size_t)(jt * 7 + (cc)) * 2048) + tid * 16; \
    uint32_t dst = sb + (s) * 65536 + tid * 16; \
    _Pragma("unroll") \
    for (int i = 0; i < 8; i++) CP16(dst + i * 4096, src + i * 4096); \
} while (0)

    // prologue: fill stages 0,1 fully; pf <- chunk 2
    CONV_LDG(0); CONV_STS(0);
    CONV_LDG(1); CONV_STS(1);
    CONV_CPA(0, 0); CP_COMMIT();
    CONV_CPA(1, 1); CP_COMMIT();
    CONV_LDG(2);
    CP_WAIT1();
    __syncthreads();

    for (int c = 0; c < 7; c++) {
        const int sn = (c + 2) % 3;
        if (c + 2 <= 6) CONV_CPA(c + 2, sn);
        CP_COMMIT();
        gemm_compute(sb, c % 3, wm, wn, lane, acc);
        if (c + 2 <= 6) CONV_STS(sn);
        if (c + 3 <= 6) CONV_LDG(c + 3);
        CP_WAIT1();
        __syncthreads();
    }

    // epilogue: g_C[(b*512 + j)*768 + r]
    const int jb = jt * 128 + wm * 64;
    const int rb = r0 + wn * 32;
#pragma unroll
    for (int mf = 0; mf < 4; mf++) {
        int j0 = jb + mf * 16 + (lane >> 2);
#pragma unroll
        for (int nf = 0; nf < 4; nf++) {
            int r = rb + nf * 8 + (lane & 3) * 2;
            *(float2*)(g_C + (size_t)(b * 512 + j0) * 768 + r)       = make_float2(acc[mf][nf][0], acc[mf][nf][1]);
            *(float2*)(g_C + (size_t)(b * 512 + j0 + 8) * 768 + r)   = make_float2(acc[mf][nf][2], acc[mf][nf][3]);
        }
    }
#undef CONV_LDG
#undef CONV_STS
#undef CONV_CPA
}

// ---------------- kernel 3: fused overlap-add + dewhiten GEMM ----------------
// out[nz][t][d] = sum_c y[t][c] * W[d][c],  y[t][c] = C[b2][j2][r] (+ C[b2-1][j2+392][r])
// m = t (A = y gather+split), n = d (B = W tiles, cp.async).
__global__ __launch_bounds__(256) void k_out_mma(float* __restrict__ out) {
    extern __shared__ char smem[];
    const uint32_t sb = smem_u32(smem);
    const int tid = threadIdx.x, lane = tid & 31, wid = tid >> 5;
    const int wm = wid >> 2, wn = wid & 3;
    const int dt = blockIdx.x;
    const int t0 = blockIdx.y * 128;
    const int nz = blockIdx.z;

    const int arow = tid >> 4;
    const int aq = tid & 15;
    const int arx = (arow & 7) << 4;

    // per-pass row bases into g_C (column base; add kk at load time)
    size_t rowbase[8];
    unsigned ovmask = 0;
#pragma unroll
    for (int p = 0; p < 8; p++) {
        int tr = t0 + arow + p * 16;
        int pp = tr + OVL;
        int b2 = pp / HOP;
        int j2 = pp - b2 * HOP;
        rowbase[p] = (size_t)(b2 * 512 + j2) * 768 + nz * CCH;
        if (j2 < OVL) ovmask |= (1u << p);
    }

    float acc[4][4][4];
#pragma unroll
    for (int i = 0; i < 4; i++)
#pragma unroll
        for (int j = 0; j < 4; j++)
#pragma unroll
            for (int q = 0; q < 4; q++) acc[i][j][q] = 0.0f;

    float4 pf[8];

#define OUT_LDG(cc) do { \
    int kk = (cc) * 64 + aq * 4; \
    _Pragma("unroll") \
    for (int p = 0; p < 8; p++) { \
        const float* a1 = g_C + rowbase[p] + kk; \
        float4 v = *(const float4*)a1; \
        if (ovmask & (1u << p)) { \
            float4 w = *(const float4*)(a1 - 92160); \
            v.x += w.x; v.y += w.y; v.z += w.z; v.w += w.w; \
        } \
        pf[p] = v; \
    } \
} while (0)
#define OUT_STS(s) do { \
    char* ahi = smem + (s) * 65536; \
    char* alo = ahi + 16384; \
    _Pragma("unroll") \
    for (int p = 0; p < 8; p++) { \
        uint2 hi, lo; split4(pf[p], hi, lo); \
        int off = (arow + p * 16) * 128 + ((aq * 8) ^ arx); \
        *(uint2*)(ahi + off) = hi; \
        *(uint2*)(alo + off) = lo; \
    } \
} while (0)
#define OUT_CPB(cc, s) do { \
    const char* src = (const char*)(g_Bw + (size_t)(dt * 6 + (cc)) * 2048) + tid * 16; \
    uint32_t dst = sb + (s) * 65536 + 32768 + tid * 16; \
    _Pragma("unroll") \
    for (int i = 0; i < 8; i++) CP16(dst + i * 4096, src + i * 4096); \
} while (0)

    OUT_LDG(0); OUT_STS(0);
    OUT_LDG(1); OUT_STS(1);
    OUT_CPB(0, 0); CP_COMMIT();
    OUT_CPB(1, 1); CP_COMMIT();
    OUT_LDG(2);
    CP_WAIT1();
    __syncthreads();

    for (int c = 0; c < 6; c++) {
        const int sn = (c + 2) % 3;
        if (c + 2 <= 5) OUT_CPB(c + 2, sn);
        CP_COMMIT();
        gemm_compute(sb, c % 3, wm, wn, lane, acc);
        if (c + 2 <= 5) OUT_STS(sn);
        if (c + 3 <= 5) OUT_LDG(c + 3);
        CP_WAIT1();
        __syncthreads();
    }

    // epilogue: out[(nz*T + t)*384 + d]
    const int tb = t0 + wm * 64;
    const int db = dt * 128 + wn * 32;
#pragma unroll
    for (int mf = 0; mf < 4; mf++) {
        int t = tb + mf * 16 + (lane >> 2);
        float* ob0 = out + ((size_t)nz * T_OUT + t) * CCH;
        float* ob1 = out + ((size_t)nz * T_OUT + t + 8) * CCH;
#pragma unroll
        for (int nf = 0; nf < 4; nf++) {
            int d = db + nf * 8 + (lane & 3) * 2;
            *(float2*)(ob0 + d) = make_float2(acc[mf][nf][0], acc[mf][nf][1]);
            *(float2*)(ob1 + d) = make_float2(acc[mf][nf][2], acc[mf][nf][3]);
        }
    }
#undef OUT_LDG
#undef OUT_STS
#undef OUT_CPB
}

// ---------------------------------------------------------------------------
extern "C" void kernel_launch(void* const* d_in, const int* in_sizes, int n_in,
                              void* d_out, int out_size) {
    const float* noise = (const float*)d_in[0];   // [768, 65656]
    const float* sstd  = (const float*)d_in[1];   // [384]
    const float* vt    = (const float*)d_in[2];   // [384, 384]
    const float* H     = (const float*)d_in[3];   // [257]
    float* out = (float*)d_out;                   // [2, 65536, 384]

    cudaFuncSetAttribute(k_conv_mma, cudaFuncAttributeMaxDynamicSharedMemorySize, 196608);
    cudaFuncSetAttribute(k_out_mma,  cudaFuncAttributeMaxDynamicSharedMemorySize, 196608);

    k_irfft<<<1, 512>>>(H);
    k_build_Bc<<<dim3(4, 7), 256>>>();
    k_build_W<<<dim3(3, 6), 256>>>(vt, sstd);
    k_conv_mma<<<dim3(168 * 6, 4), 256, 196608>>>(noise);
    k_out_mma<<<dim3(CCH / 128, T_OUT / 128, 2), 256, 196608>>>(out);
}

// round 5
// speedup vs baseline: 2.2147x; 2.2147x over previous
#include <cuda_runtime.h>
#include <cuda_fp16.h>
#include <cstdint>
#include <cstring>

// Problem constants
#define T_PADDED 65656
#define T_OUT    65536
#define NROWS    768
#define CCH      384
#define NB       168
#define HOP      392
#define OVL      120
#define NCOLS    (NROWS * NB)   // 129024

#define SWZ(x) ((x) ^ (((x) >> 3) & 0x70))

// ---------------- device globals (allocation-free rule) ----------------
__device__ float  g_h[512];
__device__ uint4  g_Bc[4 * 7 * 1024];            // circulant fp16 tiles [jt][kc], 16KB each, SW128
__device__ uint4  g_Bw[3 * 6 * 1024];            // W fp16 tiles [dt][kc]
__device__ __half g_nh[(size_t)NROWS * T_PADDED];  // noise hi fp16
__device__ __half g_nl[(size_t)NROWS * T_PADDED];  // noise lo fp16
__device__ float  g_C[(size_t)NCOLS * 512];        // [col][j], col = r*NB + b
__device__ __half g_y2h[(size_t)2 * T_OUT * CCH];  // y hi [n][t][c]
__device__ __half g_y2l[(size_t)2 * T_OUT * CCH];  // y lo

// ---------------- helpers ----------------
__device__ __forceinline__ uint32_t smem_u32(const void* p) {
    uint32_t a;
    asm("{ .reg .u64 t; cvta.to.shared.u64 t, %1; cvt.u32.u64 %0, t; }" : "=r"(a) : "l"(p));
    return a;
}
__device__ __forceinline__ void ldm4(uint32_t addr, uint32_t* r) {
    asm volatile("ldmatrix.sync.aligned.m8n8.x4.shared.b16 {%0,%1,%2,%3}, [%4];"
                 : "=r"(r[0]), "=r"(r[1]), "=r"(r[2]), "=r"(r[3]) : "r"(addr));
}
__device__ __forceinline__ void mma16816(float* c, const uint32_t* a, const uint32_t* b) {
    asm volatile("mma.sync.aligned.m16n8k16.row.col.f32.f16.f16.f32 "
                 "{%0,%1,%2,%3},{%4,%5,%6,%7},{%8,%9},{%0,%1,%2,%3};"
                 : "+f"(c[0]), "+f"(c[1]), "+f"(c[2]), "+f"(c[3])
                 : "r"(a[0]), "r"(a[1]), "r"(a[2]), "r"(a[3]), "r"(b[0]), "r"(b[1]));
}
#define CP16(s, g)     asm volatile("cp.async.cg.shared.global [%0], [%1], 16;" :: "r"(s), "l"(g))
#define CPZ(s, g, sz)  asm volatile("cp.async.cg.shared.global [%0], [%1], 16, %2;" :: "r"(s), "l"(g), "r"(sz))
#define CP_COMMIT()    asm volatile("cp.async.commit_group;" ::: "memory")
#define CP_WAIT1()     asm volatile("cp.async.wait_group 1;" ::: "memory")

// ---------------- kernel 1: h = irfft(H, 512) ----------------
__global__ void k_irfft(const float* __restrict__ H) {
    int j = threadIdx.x;
    float acc = H[0] + ((j & 1) ? -H[256] : H[256]);
    const float w = 6.283185307179586476f / 512.0f;
    for (int m = 1; m < 256; m++) {
        int ph = (m * j) & 511;
        acc += 2.0f * H[m] * cosf(w * (float)ph);
    }
    g_h[j] = acc * (1.0f / 512.0f);
}

// ---------------- kernel 1b: circulant tiles [j][k] fp16, SW128 ----------------
__global__ void k_build_Bc() {
    __shared__ float sh[512];
    int jt = blockIdx.x, kc = blockIdx.y;
    int tid = threadIdx.x;
    sh[tid] = g_h[tid]; sh[tid + 256] = g_h[tid + 256];
    __syncthreads();
    char* dst = (char*)g_Bc + (size_t)(jt * 7 + kc) * 16384;
    for (int e = tid; e < 8192; e += 256) {
        int jl = e >> 6, kl = e & 63;
        int k = kc * 64 + kl;
        float v = (k < HOP) ? sh[(jt * 128 + jl - k) & 511] : 0.0f;
        *(__half*)(dst + SWZ(jl * 128 + kl * 2)) = __float2half_rn(v);
    }
}

// ---------------- kernel 1c: W tiles [d][c] = std[c]*vt[c][d], fp16, SW128 ----------------
__global__ void k_build_W(const float* __restrict__ vt, const float* __restrict__ sstd) {
    int dt = blockIdx.x, kc = blockIdx.y;
    int tid = threadIdx.x;
    char* dst = (char*)g_Bw + (size_t)(dt * 6 + kc) * 16384;
    for (int e = tid; e < 8192; e += 256) {
        int kl = e >> 7, dl = e & 127;
        int c = kc * 64 + kl, d = dt * 128 + dl;
        float v = sstd[c] * vt[c * CCH + d];
        *(__half*)(dst + SWZ(dl * 128 + kl * 2)) = __float2half_rn(v);
    }
}

// ---------------- kernel 1d: presplit noise -> fp16 hi/lo planes ----------------
__global__ void k_split_noise(const float* __restrict__ noise) {
    size_t i = ((size_t)blockIdx.x * 256 + threadIdx.x) * 4;
    float4 v = *(const float4*)(noise + i);
    __half h0 = __float2half_rn(v.x), h1 = __float2half_rn(v.y),
           h2 = __float2half_rn(v.z), h3 = __float2half_rn(v.w);
    __half l0 = __float2half_rn(v.x - __half2float(h0));
    __half l1 = __float2half_rn(v.y - __half2float(h1));
    __half l2 = __float2half_rn(v.z - __half2float(h2));
    __half l3 = __float2half_rn(v.w - __half2float(h3));
    *(__half2*)(g_nh + i)     = __halves2half2(h0, h1);
    *(__half2*)(g_nh + i + 2) = __halves2half2(h2, h3);
    *(__half2*)(g_nl + i)     = __halves2half2(l0, l1);
    *(__half2*)(g_nl + i + 2) = __halves2half2(l2, l3);
}

// ============================================================================
// fp16 2-term warp-MMA engine. Stage s at s*49152:
//   A-hi @+0, A-lo @+16384, B-hi @+32768 (each 128 rows x 128B, SW128).
// 8 warps: wm = wid>>2 (2) x wn = wid&3 (4); warp tile 64m x 32n.
// ============================================================================
__device__ __forceinline__ void gemm16(uint32_t sb, int s, int wm, int wn,
                                       int lane, float acc[4][4][4], int nks) {
    const uint32_t sx = (lane & 7) << 4;
    const int kA_l = (lane & 16) >> 1;
    const int kB_l = lane & 8;
    const int mrow = lane & 15;
    const int nrow = (lane & 7) + ((lane & 16) >> 1);
    const uint32_t aBase = sb + s * 49152 + (wm * 64 + mrow) * 128;
    const uint32_t bBase = sb + s * 49152 + 32768 + (wn * 32 + nrow) * 128;

#pragma unroll
    for (int ks = 0; ks < 4; ks++) {
        if (ks >= nks) break;
        const uint32_t ka = ((uint32_t)(ks * 16 + kA_l) * 2) ^ sx;
        const uint32_t kb = ((uint32_t)(ks * 16 + kB_l) * 2) ^ sx;
        uint32_t bh[4][2];
#pragma unroll
        for (int p = 0; p < 2; p++) {
            uint32_t r[4];
            ldm4(bBase + p * 2048 + kb, r);
            bh[2 * p][0] = r[0]; bh[2 * p][1] = r[1];
            bh[2 * p + 1][0] = r[2]; bh[2 * p + 1][1] = r[3];
        }
#pragma unroll
        for (int mf = 0; mf < 4; mf++) {
            uint32_t ah[4], al[4];
            ldm4(aBase + mf * 2048 + ka, ah);
            ldm4(aBase + 16384 + mf * 2048 + ka, al);
#pragma unroll
            for (int nf = 0; nf < 4; nf++) {
                mma16816(acc[mf][nf], ah, bh[nf]);
                mma16816(acc[mf][nf], al, bh[nf]);
            }
        }
    }
}

// ---------------- kernel 2: conv GEMM ----------------
// D[col][j] = sum_k noise[r, b*HOP + k] * circ[j, k];  m = col (A = noise hi/lo,
// cp.async from presplit planes), n = j (B = circulant tiles, cp.async).
__global__ __launch_bounds__(256, 2) void k_conv_mma() {
    extern __shared__ char smem[];
    const uint32_t sb = smem_u32(smem);
    const int tid = threadIdx.x, lane = tid & 31, wid = tid >> 5;
    const int wm = wid >> 2, wn = wid & 3;
    const int m0 = blockIdx.x * 128;      // col base
    const int jt = blockIdx.y;

    const int q8 = (tid & 7) * 8;         // k offset (halves) within chunk
    const int qx = (tid & 7) * 16;        // byte offset within row
    uint32_t rowoff[4];
    const __half* nhb[4];
    const __half* nlb[4];
    int krel[4];
#pragma unroll
    for (int p = 0; p < 4; p++) {
        int row = (tid >> 3) + p * 32;
        rowoff[p] = row * 128 + (qx ^ ((row & 7) << 4));
        int col = m0 + row;
        int r = col / NB, b = col - r * NB;
        nhb[p] = g_nh + (size_t)r * T_PADDED + b * HOP;
        nlb[p] = g_nl + (size_t)r * T_PADDED + b * HOP;
        krel[p] = T_PADDED - b * HOP;
    }

    float acc[4][4][4];
#pragma unroll
    for (int i = 0; i < 4; i++)
#pragma unroll
        for (int j = 0; j < 4; j++)
#pragma unroll
            for (int q = 0; q < 4; q++) acc[i][j][q] = 0.0f;

#define CONV_ISSUE(cc, s) do { \
    const int kk = (cc) * 64 + q8; \
    _Pragma("unroll") \
    for (int p = 0; p < 4; p++) { \
        unsigned sz = (kk < krel[p]) ? 16u : 0u; \
        uint32_t d0 = sb + (s) * 49152 + rowoff[p]; \
        CPZ(d0,         nhb[p] + kk, sz); \
        CPZ(d0 + 16384, nlb[p] + kk, sz); \
    } \
    const char* srcB = (const char*)(g_Bc + (size_t)(jt * 7 + (cc)) * 1024) + tid * 16; \
    uint32_t dB = sb + (s) * 49152 + 32768 + tid * 16; \
    _Pragma("unroll") \
    for (int i = 0; i < 4; i++) CP16(dB + i * 4096, srcB + i * 4096); \
} while (0)

    CONV_ISSUE(0, 0); CP_COMMIT();
    CONV_ISSUE(1, 1); CP_COMMIT();
    CP_WAIT1();
    __syncthreads();

    for (int c = 0; c < 7; c++) {
        gemm16(sb, c & 1, wm, wn, lane, acc, (c == 6) ? 1 : 4);
        __syncthreads();
        if (c + 2 < 7) CONV_ISSUE(c + 2, c & 1);
        CP_COMMIT();
        CP_WAIT1();
        __syncthreads();
    }

    // epilogue: g_C[col][j] (n-pairs contiguous along j)
    const int colb = m0 + wm * 64;
    const int jb = jt * 128 + wn * 32;
#pragma unroll
    for (int mf = 0; mf < 4; mf++) {
        int col0 = colb + mf * 16 + (lane >> 2);
#pragma unroll
        for (int nf = 0; nf < 4; nf++) {
            int j = jb + nf * 8 + (lane & 3) * 2;
            *(float2*)(g_C + (size_t)col0 * 512 + j)       = make_float2(acc[mf][nf][0], acc[mf][nf][1]);
            *(float2*)(g_C + (size_t)(col0 + 8) * 512 + j) = make_float2(acc[mf][nf][2], acc[mf][nf][3]);
        }
    }
#undef CONV_ISSUE
}

// ---------------- kernel 3: overlap-add combine + transpose + fp16 split ----------------
__global__ __launch_bounds__(256) void k_combineT() {
    __shared__ float stage[64][65];
    const int tid = threadIdx.x;
    const int t0 = blockIdx.x * 64;
    const int c0 = blockIdx.y * 64;
    const int nz = blockIdx.z;
    {
        int t_l = tid & 63;
        int t = t0 + t_l;
        int p = t + OVL;
        int b2 = p / HOP;
        int j2 = p - b2 * HOP;
        for (int cc = tid >> 6; cc < 64; cc += 4) {
            int r = nz * CCH + c0 + cc;
            size_t col = (size_t)r * NB + b2;
            float v = g_C[col * 512 + j2];
            if (j2 < OVL) v += g_C[(col - 1) * 512 + j2 + HOP];
            stage[cc][t_l] = v;
        }
    }
    __syncthreads();
    {
        int c_l = tid & 63;
        for (int tt = tid >> 6; tt < 64; tt += 4) {
            float v = stage[c_l][tt];
            __half h = __float2half_rn(v);
            __half l = __float2half_rn(v - __half2float(h));
            size_t idx = ((size_t)nz * T_OUT + t0 + tt) * CCH + c0 + c_l;
            g_y2h[idx] = h;
            g_y2l[idx] = l;
        }
    }
}

// ---------------- kernel 4: out GEMM: out[t][d] = sum_c y[t][c] W[d][c] ----------------
__global__ __launch_bounds__(256, 2) void k_out_mma(float* __restrict__ out) {
    extern __shared__ char smem[];
    const uint32_t sb = smem_u32(smem);
    const int tid = threadIdx.x, lane = tid & 31, wid = tid >> 5;
    const int wm = wid >> 2, wn = wid & 3;
    const int dt = blockIdx.x;
    const int t0 = blockIdx.y * 128;
    const int nz = blockIdx.z;

    const int q8 = (tid & 7) * 8;
    const int qx = (tid & 7) * 16;
    uint32_t rowoff[4];
    const __half* yhb[4];
    const __half* ylb[4];
#pragma unroll
    for (int p = 0; p < 4; p++) {
        int row = (tid >> 3) + p * 32;
        rowoff[p] = row * 128 + (qx ^ ((row & 7) << 4));
        size_t base = ((size_t)nz * T_OUT + t0 + row) * CCH;
        yhb[p] = g_y2h + base;
        ylb[p] = g_y2l + base;
    }

    float acc[4][4][4];
#pragma unroll
    for (int i = 0; i < 4; i++)
#pragma unroll
        for (int j = 0; j < 4; j++)
#pragma unroll
            for (int q = 0; q < 4; q++) acc[i][j][q] = 0.0f;

#define OUT_ISSUE(cc, s) do { \
    const int kk = (cc) * 64 + q8; \
    _Pragma("unroll") \
    for (int p = 0; p < 4; p++) { \
        uint32_t d0 = sb + (s) * 49152 + rowoff[p]; \
        CP16(d0,         yhb[p] + kk); \
        CP16(d0 + 16384, ylb[p] + kk); \
    } \
    const char* srcB = (const char*)(g_Bw + (size_t)(dt * 6 + (cc)) * 1024) + tid * 16; \
    uint32_t dB = sb + (s) * 49152 + 32768 + tid * 16; \
    _Pragma("unroll") \
    for (int i = 0; i < 4; i++) CP16(dB + i * 4096, srcB + i * 4096); \
} while (0)

    OUT_ISSUE(0, 0); CP_COMMIT();
    OUT_ISSUE(1, 1); CP_COMMIT();
    CP_WAIT1();
    __syncthreads();

    for (int c = 0; c < 6; c++) {
        gemm16(sb, c & 1, wm, wn, lane, acc, 4);
        __syncthreads();
        if (c + 2 < 6) OUT_ISSUE(c + 2, c & 1);
        CP_COMMIT();
        CP_WAIT1();
        __syncthreads();
    }

    // epilogue: out[(nz*T + t)*384 + d]
    const int tb = t0 + wm * 64;
    const int db = dt * 128 + wn * 32;
#pragma unroll
    for (int mf = 0; mf < 4; mf++) {
        int t = tb + mf * 16 + (lane >> 2);
        float* ob0 = out + ((size_t)nz * T_OUT + t) * CCH;
        float* ob1 = out + ((size_t)nz * T_OUT + t + 8) * CCH;
#pragma unroll
        for (int nf = 0; nf < 4; nf++) {
            int d = db + nf * 8 + (lane & 3) * 2;
            *(float2*)(ob0 + d) = make_float2(acc[mf][nf][0], acc[mf][nf][1]);
            *(float2*)(ob1 + d) = make_float2(acc[mf][nf][2], acc[mf][nf][3]);
        }
    }
#undef OUT_ISSUE
}

// ---------------------------------------------------------------------------
extern "C" void kernel_launch(void* const* d_in, const int* in_sizes, int n_in,
                              void* d_out, int out_size) {
    const float* noise = (const float*)d_in[0];   // [768, 65656]
    const float* sstd  = (const float*)d_in[1];   // [384]
    const float* vt    = (const float*)d_in[2];   // [384, 384]
    const float* H     = (const float*)d_in[3];   // [257]
    float* out = (float*)d_out;                   // [2, 65536, 384]

    cudaFuncSetAttribute(k_conv_mma, cudaFuncAttributeMaxDynamicSharedMemorySize, 98304);
    cudaFuncSetAttribute(k_out_mma,  cudaFuncAttributeMaxDynamicSharedMemorySize, 98304);

    k_irfft<<<1, 512>>>(H);
    k_build_Bc<<<dim3(4, 7), 256>>>();
    k_build_W<<<dim3(3, 6), 256>>>(vt, sstd);
    k_split_noise<<<(NROWS * T_PADDED) / 1024, 256>>>(noise);
    k_conv_mma<<<dim3(NCOLS / 128, 4), 256, 98304>>>();
    k_combineT<<<dim3(T_OUT / 64, CCH / 64, 2), 256>>>();
    k_out_mma<<<dim3(CCH / 128, T_OUT / 128, 2), 256, 98304>>>(out);
}

// round 6
// speedup vs baseline: 2.7869x; 1.2584x over previous
#include <cuda_runtime.h>
#include <cuda_fp16.h>
#include <cstdint>
#include <cstring>

// Problem constants
#define T_PADDED 65656
#define T_OUT    65536
#define NROWS    768
#define CCH      384
#define NB       168
#define HOP      392
#define OVL      120
#define NCOLS    (NROWS * NB)   // 129024

#define SWZ(x) ((x) ^ (((x) >> 3) & 0x70))

// ---------------- device globals (allocation-free rule) ----------------
__device__ float  g_h[512];
__device__ uint4  g_Bc[4 * 7 * 1024];              // circulant fp16 tiles [jt][kc], 16KB, SW128
__device__ uint4  g_Bw[3 * 6 * 1024];              // W fp16 tiles [dt][kc]
__device__ __half g_nh[(size_t)NROWS * T_PADDED];  // noise fp16 (rn)
__device__ float  g_C[(size_t)NCOLS * 512];        // [col][j], col = r*NB + b
__device__ __half g_y2[(size_t)2 * T_OUT * CCH];   // y fp16 (rn) [n][t][c]

// ---------------- helpers ----------------
__device__ __forceinline__ uint32_t smem_u32(const void* p) {
    uint32_t a;
    asm("{ .reg .u64 t; cvta.to.shared.u64 t, %1; cvt.u32.u64 %0, t; }" : "=r"(a) : "l"(p));
    return a;
}
__device__ __forceinline__ void ldm4(uint32_t addr, uint32_t* r) {
    asm volatile("ldmatrix.sync.aligned.m8n8.x4.shared.b16 {%0,%1,%2,%3}, [%4];"
                 : "=r"(r[0]), "=r"(r[1]), "=r"(r[2]), "=r"(r[3]) : "r"(addr));
}
__device__ __forceinline__ void mma16816(float* c, const uint32_t* a, const uint32_t* b) {
    asm volatile("mma.sync.aligned.m16n8k16.row.col.f32.f16.f16.f32 "
                 "{%0,%1,%2,%3},{%4,%5,%6,%7},{%8,%9},{%0,%1,%2,%3};"
                 : "+f"(c[0]), "+f"(c[1]), "+f"(c[2]), "+f"(c[3])
                 : "r"(a[0]), "r"(a[1]), "r"(a[2]), "r"(a[3]), "r"(b[0]), "r"(b[1]));
}
#define CP16(s, g)     asm volatile("cp.async.cg.shared.global [%0], [%1], 16;" :: "r"(s), "l"(g))
#define CPZ(s, g, sz)  asm volatile("cp.async.cg.shared.global [%0], [%1], 16, %2;" :: "r"(s), "l"(g), "r"(sz))
#define CP_COMMIT()    asm volatile("cp.async.commit_group;" ::: "memory")
#define CP_WAIT2()     asm volatile("cp.async.wait_group 2;" ::: "memory")

// ---------------- kernel 1: h = irfft(H, 512) ----------------
__global__ void k_irfft(const float* __restrict__ H) {
    int j = threadIdx.x;
    float acc = H[0] + ((j & 1) ? -H[256] : H[256]);
    const float w = 6.283185307179586476f / 512.0f;
    for (int m = 1; m < 256; m++) {
        int ph = (m * j) & 511;
        acc += 2.0f * H[m] * cosf(w * (float)ph);
    }
    g_h[j] = acc * (1.0f / 512.0f);
}

// ---------------- kernel 1b: circulant tiles [j][k] fp16, SW128 ----------------
__global__ void k_build_Bc() {
    __shared__ float sh[512];
    int jt = blockIdx.x, kc = blockIdx.y;
    int tid = threadIdx.x;
    sh[tid] = g_h[tid]; sh[tid + 256] = g_h[tid + 256];
    __syncthreads();
    char* dst = (char*)g_Bc + (size_t)(jt * 7 + kc) * 16384;
    for (int e = tid; e < 8192; e += 256) {
        int jl = e >> 6, kl = e & 63;
        int k = kc * 64 + kl;
        float v = (k < HOP) ? sh[(jt * 128 + jl - k) & 511] : 0.0f;
        *(__half*)(dst + SWZ(jl * 128 + kl * 2)) = __float2half_rn(v);
    }
}

// ---------------- kernel 1c: W tiles [d][c] = std[c]*vt[c][d], fp16, SW128 ----------------
__global__ void k_build_W(const float* __restrict__ vt, const float* __restrict__ sstd) {
    int dt = blockIdx.x, kc = blockIdx.y;
    int tid = threadIdx.x;
    char* dst = (char*)g_Bw + (size_t)(dt * 6 + kc) * 16384;
    for (int e = tid; e < 8192; e += 256) {
        int kl = e >> 7, dl = e & 127;
        int c = kc * 64 + kl, d = dt * 128 + dl;
        float v = sstd[c] * vt[c * CCH + d];
        *(__half*)(dst + SWZ(dl * 128 + kl * 2)) = __float2half_rn(v);
    }
}

// ---------------- kernel 1d: noise -> fp16 plane ----------------
__global__ void k_trunc_noise(const float* __restrict__ noise) {
    size_t i = ((size_t)blockIdx.x * 256 + threadIdx.x) * 4;
    float4 v = *(const float4*)(noise + i);
    *(__half2*)(g_nh + i)     = __halves2half2(__float2half_rn(v.x), __float2half_rn(v.y));
    *(__half2*)(g_nh + i + 2) = __halves2half2(__float2half_rn(v.z), __float2half_rn(v.w));
}

// ============================================================================
// fp16 warp-MMA engine, single plane each side. Stage s at s*32768:
//   A @+0 (128 rows x 128B, SW128), B @+16384.
// 8 warps: wm = wid>>2 (2) x wn = wid&3 (4); warp tile 64m x 32n.
// ============================================================================
__device__ __forceinline__ void gemm16(uint32_t sb, int s, int wm, int wn,
                                       int lane, float acc[4][4][4], int nks) {
    const uint32_t sx = (lane & 7) << 4;
    const int kA_l = (lane & 16) >> 1;
    const int kB_l = lane & 8;
    const int mrow = lane & 15;
    const int nrow = (lane & 7) + ((lane & 16) >> 1);
    const uint32_t aBase = sb + s * 32768 + (wm * 64 + mrow) * 128;
    const uint32_t bBase = sb + s * 32768 + 16384 + (wn * 32 + nrow) * 128;

#pragma unroll
    for (int ks = 0; ks < 4; ks++) {
        if (ks >= nks) break;
        const uint32_t ka = ((uint32_t)(ks * 16 + kA_l) * 2) ^ sx;
        const uint32_t kb = ((uint32_t)(ks * 16 + kB_l) * 2) ^ sx;
        uint32_t bh[4][2];
#pragma unroll
        for (int p = 0; p < 2; p++) {
            uint32_t r[4];
            ldm4(bBase + p * 2048 + kb, r);
            bh[2 * p][0] = r[0]; bh[2 * p][1] = r[1];
            bh[2 * p + 1][0] = r[2]; bh[2 * p + 1][1] = r[3];
        }
#pragma unroll
        for (int mf = 0; mf < 4; mf++) {
            uint32_t ah[4];
            ldm4(aBase + mf * 2048 + ka, ah);
#pragma unroll
            for (int nf = 0; nf < 4; nf++)
                mma16816(acc[mf][nf], ah, bh[nf]);
        }
    }
}

// ---------------- kernel 2: conv GEMM ----------------
// D[col][j] = sum_k noise[r, b*HOP + k] * circ[j, k]; m=col (A=noise fp16 plane),
// n=j (B=circulant tiles). 3-stage cp.async pipeline.
__global__ __launch_bounds__(256, 2) void k_conv_mma() {
    extern __shared__ char smem[];
    const uint32_t sb = smem_u32(smem);
    const int tid = threadIdx.x, lane = tid & 31, wid = tid >> 5;
    const int wm = wid >> 2, wn = wid & 3;
    const int m0 = blockIdx.x * 128;      // col base
    const int jt = blockIdx.y;

    // A fill mapping: thread -> (row = tid>>1, 64B segment = tid&1)
    const int row = tid >> 1;
    const int seg = (tid & 1) * 64;       // byte offset in row
    const uint32_t rowbase = row * 128;
    const uint32_t rxor = (row & 7) << 4;
    const int col = m0 + row;
    const int r = col / NB, b = col - r * NB;
    const __half* nrow_ptr = g_nh + (size_t)r * T_PADDED + b * HOP;
    const int krel = T_PADDED - b * HOP;  // valid halves from chunk origin

    float acc[4][4][4];
#pragma unroll
    for (int i = 0; i < 4; i++)
#pragma unroll
        for (int j = 0; j < 4; j++)
#pragma unroll
            for (int q = 0; q < 4; q++) acc[i][j][q] = 0.0f;

#define CONV_ISSUE(cc, s) do { \
    const int kk = (cc) * 64 + seg / 2; \
    _Pragma("unroll") \
    for (int i = 0; i < 4; i++) { \
        unsigned sz = (kk + i * 8 < krel) ? 16u : 0u; \
        CPZ(sb + (s) * 32768 + rowbase + ((seg + i * 16) ^ rxor), nrow_ptr + kk + i * 8, sz); \
    } \
    const char* srcB = (const char*)(g_Bc + (size_t)(jt * 7 + (cc)) * 1024) + tid * 16; \
    uint32_t dB = sb + (s) * 32768 + 16384 + tid * 16; \
    _Pragma("unroll") \
    for (int i = 0; i < 4; i++) CP16(dB + i * 4096, srcB + i * 4096); \
} while (0)

    CONV_ISSUE(0, 0); CP_COMMIT();
    CONV_ISSUE(1, 1); CP_COMMIT();
    CONV_ISSUE(2, 2); CP_COMMIT();
    CP_WAIT2();
    __syncthreads();

    for (int c = 0; c < 7; c++) {
        gemm16(sb, c % 3, wm, wn, lane, acc, (c == 6) ? 1 : 4);
        __syncthreads();
        if (c + 3 < 7) CONV_ISSUE(c + 3, c % 3);
        CP_COMMIT();
        CP_WAIT2();
        __syncthreads();
    }

    // epilogue: g_C[col][j]
    const int colb = m0 + wm * 64;
    const int jb = jt * 128 + wn * 32;
#pragma unroll
    for (int mf = 0; mf < 4; mf++) {
        int col0 = colb + mf * 16 + (lane >> 2);
#pragma unroll
        for (int nf = 0; nf < 4; nf++) {
            int j = jb + nf * 8 + (lane & 3) * 2;
            *(float2*)(g_C + (size_t)col0 * 512 + j)       = make_float2(acc[mf][nf][0], acc[mf][nf][1]);
            *(float2*)(g_C + (size_t)(col0 + 8) * 512 + j) = make_float2(acc[mf][nf][2], acc[mf][nf][3]);
        }
    }
#undef CONV_ISSUE
}

// ---------------- kernel 3: overlap-add combine + transpose + fp16 ----------------
__global__ __launch_bounds__(256) void k_combineT() {
    __shared__ float stage[64][65];
    const int tid = threadIdx.x;
    const int t0 = blockIdx.x * 64;
    const int c0 = blockIdx.y * 64;
    const int nz = blockIdx.z;
    {
        int t_l = tid & 63;
        int t = t0 + t_l;
        int p = t + OVL;
        int b2 = p / HOP;
        int j2 = p - b2 * HOP;
        for (int cc = tid >> 6; cc < 64; cc += 4) {
            int r = nz * CCH + c0 + cc;
            size_t col = (size_t)r * NB + b2;
            float v = g_C[col * 512 + j2];
            if (j2 < OVL) v += g_C[(col - 1) * 512 + j2 + HOP];
            stage[cc][t_l] = v;
        }
    }
    __syncthreads();
    {
        int c_l = tid & 63;
        for (int tt = tid >> 6; tt < 64; tt += 4)
            g_y2[((size_t)nz * T_OUT + t0 + tt) * CCH + c0 + c_l] =
                __float2half_rn(stage[c_l][tt]);
    }
}

// ---------------- kernel 4: out GEMM: out[t][d] = sum_c y[t][c] W[d][c] ----------------
__global__ __launch_bounds__(256, 2) void k_out_mma(float* __restrict__ out) {
    extern __shared__ char smem[];
    const uint32_t sb = smem_u32(smem);
    const int tid = threadIdx.x, lane = tid & 31, wid = tid >> 5;
    const int wm = wid >> 2, wn = wid & 3;
    const int dt = blockIdx.x;
    const int t0 = blockIdx.y * 128;
    const int nz = blockIdx.z;

    const int row = tid >> 1;
    const int seg = (tid & 1) * 64;
    const uint32_t rowbase = row * 128;
    const uint32_t rxor = (row & 7) << 4;
    const __half* yrow_ptr = g_y2 + ((size_t)nz * T_OUT + t0 + row) * CCH;

    float acc[4][4][4];
#pragma unroll
    for (int i = 0; i < 4; i++)
#pragma unroll
        for (int j = 0; j < 4; j++)
#pragma unroll
            for (int q = 0; q < 4; q++) acc[i][j][q] = 0.0f;

#define OUT_ISSUE(cc, s) do { \
    const int kk = (cc) * 64 + seg / 2; \
    _Pragma("unroll") \
    for (int i = 0; i < 4; i++) \
        CP16(sb + (s) * 32768 + rowbase + ((seg + i * 16) ^ rxor), yrow_ptr + kk + i * 8); \
    const char* srcB = (const char*)(g_Bw + (size_t)(dt * 6 + (cc)) * 1024) + tid * 16; \
    uint32_t dB = sb + (s) * 32768 + 16384 + tid * 16; \
    _Pragma("unroll") \
    for (int i = 0; i < 4; i++) CP16(dB + i * 4096, srcB + i * 4096); \
} while (0)

    OUT_ISSUE(0, 0); CP_COMMIT();
    OUT_ISSUE(1, 1); CP_COMMIT();
    OUT_ISSUE(2, 2); CP_COMMIT();
    CP_WAIT2();
    __syncthreads();

    for (int c = 0; c < 6; c++) {
        gemm16(sb, c % 3, wm, wn, lane, acc, 4);
        __syncthreads();
        if (c + 3 < 6) OUT_ISSUE(c + 3, c % 3);
        CP_COMMIT();
        CP_WAIT2();
        __syncthreads();
    }

    // epilogue: out[(nz*T + t)*384 + d]
    const int tb = t0 + wm * 64;
    const int db = dt * 128 + wn * 32;
#pragma unroll
    for (int mf = 0; mf < 4; mf++) {
        int t = tb + mf * 16 + (lane >> 2);
        float* ob0 = out + ((size_t)nz * T_OUT + t) * CCH;
        float* ob1 = out + ((size_t)nz * T_OUT + t + 8) * CCH;
#pragma unroll
        for (int nf = 0; nf < 4; nf++) {
            int d = db + nf * 8 + (lane & 3) * 2;
            *(float2*)(ob0 + d) = make_float2(acc[mf][nf][0], acc[mf][nf][1]);
            *(float2*)(ob1 + d) = make_float2(acc[mf][nf][2], acc[mf][nf][3]);
        }
    }
#undef OUT_ISSUE
}

// ---------------------------------------------------------------------------
extern "C" void kernel_launch(void* const* d_in, const int* in_sizes, int n_in,
                              void* d_out, int out_size) {
    const float* noise = (const float*)d_in[0];   // [768, 65656]
    const float* sstd  = (const float*)d_in[1];   // [384]
    const float* vt    = (const float*)d_in[2];   // [384, 384]
    const float* H     = (const float*)d_in[3];   // [257]
    float* out = (float*)d_out;                   // [2, 65536, 384]

    cudaFuncSetAttribute(k_conv_mma, cudaFuncAttributeMaxDynamicSharedMemorySize, 98304);
    cudaFuncSetAttribute(k_out_mma,  cudaFuncAttributeMaxDynamicSharedMemorySize, 98304);

    k_irfft<<<1, 512>>>(H);
    k_build_Bc<<<dim3(4, 7), 256>>>();
    k_build_W<<<dim3(3, 6), 256>>>(vt, sstd);
    k_trunc_noise<<<(NROWS * T_PADDED) / 1024, 256>>>(noise);
    k_conv_mma<<<dim3(NCOLS / 128, 4), 256, 98304>>>();
    k_combineT<<<dim3(T_OUT / 64, CCH / 64, 2), 256>>>();
    k_out_mma<<<dim3(CCH / 128, T_OUT / 128, 2), 256, 98304>>>(out);
}

// round 7
// speedup vs baseline: 2.8011x; 1.0051x over previous
#include <cuda_runtime.h>
#include <cuda_fp16.h>
#include <cstdint>
#include <cstring>

// Problem constants
#define T_PADDED 65656
#define T_OUT    65536
#define NROWS    768
#define CCH      384
#define NB       168
#define HOP      392
#define OVL      120
#define NCOLS    (NROWS * NB)   // 129024

#define SWZ(x) ((x) ^ (((x) >> 3) & 0x70))

// ---------------- device globals (allocation-free rule) ----------------
__device__ float  g_h[512];
__device__ uint4  g_Bc[4 * 7 * 1024];              // circulant fp16 tiles [jt][kc], 16KB, SW128
__device__ uint4  g_Bw[3 * 6 * 1024];              // W fp16 tiles [dt][kc]
__device__ __half g_nh[(size_t)NROWS * T_PADDED];  // noise fp16 (rn)
__device__ __half g_C[(size_t)NCOLS * 512];        // fp16 [col][j], col = r*NB + b
__device__ __half g_y2[(size_t)2 * T_OUT * CCH];   // y fp16 (rn) [n][t][c]

// ---------------- helpers ----------------
__device__ __forceinline__ uint32_t smem_u32(const void* p) {
    uint32_t a;
    asm("{ .reg .u64 t; cvta.to.shared.u64 t, %1; cvt.u32.u64 %0, t; }" : "=r"(a) : "l"(p));
    return a;
}
__device__ __forceinline__ void ldm4(uint32_t addr, uint32_t* r) {
    asm volatile("ldmatrix.sync.aligned.m8n8.x4.shared.b16 {%0,%1,%2,%3}, [%4];"
                 : "=r"(r[0]), "=r"(r[1]), "=r"(r[2]), "=r"(r[3]) : "r"(addr));
}
__device__ __forceinline__ void mma16816(float* c, const uint32_t* a, const uint32_t* b) {
    asm volatile("mma.sync.aligned.m16n8k16.row.col.f32.f16.f16.f32 "
                 "{%0,%1,%2,%3},{%4,%5,%6,%7},{%8,%9},{%0,%1,%2,%3};"
                 : "+f"(c[0]), "+f"(c[1]), "+f"(c[2]), "+f"(c[3])
                 : "r"(a[0]), "r"(a[1]), "r"(a[2]), "r"(a[3]), "r"(b[0]), "r"(b[1]));
}
#define CP16(s, g)     asm volatile("cp.async.cg.shared.global [%0], [%1], 16;" :: "r"(s), "l"(g))
#define CPZ(s, g, sz)  asm volatile("cp.async.cg.shared.global [%0], [%1], 16, %2;" :: "r"(s), "l"(g), "r"(sz))
#define CP_COMMIT()    asm volatile("cp.async.commit_group;" ::: "memory")
#define CP_WAIT1()     asm volatile("cp.async.wait_group 1;" ::: "memory")

// ---------------- kernel 1: h = irfft(H, 512) ----------------
__global__ void k_irfft(const float* __restrict__ H) {
    int j = threadIdx.x;
    float acc = H[0] + ((j & 1) ? -H[256] : H[256]);
    const float w = 6.283185307179586476f / 512.0f;
    for (int m = 1; m < 256; m++) {
        int ph = (m * j) & 511;
        acc += 2.0f * H[m] * cosf(w * (float)ph);
    }
    g_h[j] = acc * (1.0f / 512.0f);
}

// ---------------- kernel 1b: circulant tiles [j][k] fp16, SW128 ----------------
__global__ void k_build_Bc() {
    __shared__ float sh[512];
    int jt = blockIdx.x, kc = blockIdx.y;
    int tid = threadIdx.x;
    sh[tid] = g_h[tid]; sh[tid + 256] = g_h[tid + 256];
    __syncthreads();
    char* dst = (char*)g_Bc + (size_t)(jt * 7 + kc) * 16384;
    for (int e = tid; e < 8192; e += 256) {
        int jl = e >> 6, kl = e & 63;
        int k = kc * 64 + kl;
        float v = (k < HOP) ? sh[(jt * 128 + jl - k) & 511] : 0.0f;
        *(__half*)(dst + SWZ(jl * 128 + kl * 2)) = __float2half_rn(v);
    }
}

// ---------------- kernel 1c: W tiles [d][c] = std[c]*vt[c][d], fp16, SW128 ----------------
__global__ void k_build_W(const float* __restrict__ vt, const float* __restrict__ sstd) {
    int dt = blockIdx.x, kc = blockIdx.y;
    int tid = threadIdx.x;
    char* dst = (char*)g_Bw + (size_t)(dt * 6 + kc) * 16384;
    for (int e = tid; e < 8192; e += 256) {
        int kl = e >> 7, dl = e & 127;
        int c = kc * 64 + kl, d = dt * 128 + dl;
        float v = sstd[c] * vt[c * CCH + d];
        *(__half*)(dst + SWZ(dl * 128 + kl * 2)) = __float2half_rn(v);
    }
}

// ---------------- kernel 1d: noise -> fp16 plane ----------------
__global__ void k_trunc_noise(const float* __restrict__ noise) {
    size_t i = ((size_t)blockIdx.x * 256 + threadIdx.x) * 4;
    float4 v = *(const float4*)(noise + i);
    *(__half2*)(g_nh + i)     = __halves2half2(__float2half_rn(v.x), __float2half_rn(v.y));
    *(__half2*)(g_nh + i + 2) = __halves2half2(__float2half_rn(v.z), __float2half_rn(v.w));
}

// ============================================================================
// fp16 warp-MMA engine. Stage s at s*32768: A @+0 (128x128B, SW128), B @+16384.
// 8 warps: wm = wid>>2 (2) x wn = wid&3 (4); warp tile 64m x 32n.
// ============================================================================
__device__ __forceinline__ void gemm16(uint32_t sb, int s, int wm, int wn,
                                       int lane, float acc[4][4][4], int nks) {
    const uint32_t sx = (lane & 7) << 4;
    const int kA_l = (lane & 16) >> 1;
    const int kB_l = lane & 8;
    const int mrow = lane & 15;
    const int nrow = (lane & 7) + ((lane & 16) >> 1);
    const uint32_t aBase = sb + s * 32768 + (wm * 64 + mrow) * 128;
    const uint32_t bBase = sb + s * 32768 + 16384 + (wn * 32 + nrow) * 128;

#pragma unroll
    for (int ks = 0; ks < 4; ks++) {
        if (ks >= nks) break;
        const uint32_t ka = ((uint32_t)(ks * 16 + kA_l) * 2) ^ sx;
        const uint32_t kb = ((uint32_t)(ks * 16 + kB_l) * 2) ^ sx;
        uint32_t bh[4][2];
#pragma unroll
        for (int p = 0; p < 2; p++) {
            uint32_t r[4];
            ldm4(bBase + p * 2048 + kb, r);
            bh[2 * p][0] = r[0]; bh[2 * p][1] = r[1];
            bh[2 * p + 1][0] = r[2]; bh[2 * p + 1][1] = r[3];
        }
#pragma unroll
        for (int mf = 0; mf < 4; mf++) {
            uint32_t ah[4];
            ldm4(aBase + mf * 2048 + ka, ah);
#pragma unroll
            for (int nf = 0; nf < 4; nf++)
                mma16816(acc[mf][nf], ah, bh[nf]);
        }
    }
}

// ---------------- kernel 2: conv GEMM ----------------
// D[col][j] = sum_k noise[r, b*HOP + k] * circ[j, k]; m=col, n=j.
// 3-stage cp.async pipeline, single sync per chunk (issue distance 2).
__global__ __launch_bounds__(256, 2) void k_conv_mma() {
    extern __shared__ char smem[];
    const uint32_t sb = smem_u32(smem);
    const int tid = threadIdx.x, lane = tid & 31, wid = tid >> 5;
    const int wm = wid >> 2, wn = wid & 3;
    const int m0 = blockIdx.x * 128;      // col base
    const int jt = blockIdx.y;

    const int row = tid >> 1;
    const int seg = (tid & 1) * 64;       // byte offset in row
    const uint32_t rowbase = row * 128;
    const uint32_t rxor = (row & 7) << 4;
    const int col = m0 + row;
    const int r = col / NB, b = col - r * NB;
    const __half* nrow_ptr = g_nh + (size_t)r * T_PADDED + b * HOP;
    const int krel = T_PADDED - b * HOP;

    float acc[4][4][4];
#pragma unroll
    for (int i = 0; i < 4; i++)
#pragma unroll
        for (int j = 0; j < 4; j++)
#pragma unroll
            for (int q = 0; q < 4; q++) acc[i][j][q] = 0.0f;

#define CONV_ISSUE(cc, s) do { \
    const int kk = (cc) * 64 + seg / 2; \
    _Pragma("unroll") \
    for (int i = 0; i < 4; i++) { \
        unsigned sz = (kk + i * 8 < krel) ? 16u : 0u; \
        CPZ(sb + (s) * 32768 + rowbase + ((seg + i * 16) ^ rxor), nrow_ptr + kk + i * 8, sz); \
    } \
    const char* srcB = (const char*)(g_Bc + (size_t)(jt * 7 + (cc)) * 1024) + tid * 16; \
    uint32_t dB = sb + (s) * 32768 + 16384 + tid * 16; \
    _Pragma("unroll") \
    for (int i = 0; i < 4; i++) CP16(dB + i * 4096, srcB + i * 4096); \
} while (0)

    CONV_ISSUE(0, 0); CP_COMMIT();
    CONV_ISSUE(1, 1); CP_COMMIT();

    for (int c = 0; c < 7; c++) {
        CP_WAIT1();                        // chunk c landed
        __syncthreads();                   // all warps done with stage (c+2)%3
        if (c + 2 < 7) CONV_ISSUE(c + 2, (c + 2) % 3);
        CP_COMMIT();
        gemm16(sb, c % 3, wm, wn, lane, acc, (c == 6) ? 1 : 4);
    }

    // epilogue: g_C[col][j] fp16
    const int colb = m0 + wm * 64;
    const int jb = jt * 128 + wn * 32;
#pragma unroll
    for (int mf = 0; mf < 4; mf++) {
        int col0 = colb + mf * 16 + (lane >> 2);
#pragma unroll
        for (int nf = 0; nf < 4; nf++) {
            int j = jb + nf * 8 + (lane & 3) * 2;
            *(__half2*)(g_C + (size_t)col0 * 512 + j) =
                __floats2half2_rn(acc[mf][nf][0], acc[mf][nf][1]);
            *(__half2*)(g_C + (size_t)(col0 + 8) * 512 + j) =
                __floats2half2_rn(acc[mf][nf][2], acc[mf][nf][3]);
        }
    }
#undef CONV_ISSUE
}

// ---------------- kernel 3: overlap-add combine + transpose + fp16 ----------------
__global__ __launch_bounds__(256) void k_combineT() {
    __shared__ float stage[64][65];
    const int tid = threadIdx.x;
    const int t0 = blockIdx.x * 64;
    const int c0 = blockIdx.y * 64;
    const int nz = blockIdx.z;
    {
        int t_l = tid & 63;
        int t = t0 + t_l;
        int p = t + OVL;
        int b2 = p / HOP;
        int j2 = p - b2 * HOP;
        for (int cc = tid >> 6; cc < 64; cc += 4) {
            int r = nz * CCH + c0 + cc;
            size_t col = (size_t)r * NB + b2;
            float v = __half2float(g_C[col * 512 + j2]);
            if (j2 < OVL) v += __half2float(g_C[(col - 1) * 512 + j2 + HOP]);
            stage[cc][t_l] = v;
        }
    }
    __syncthreads();
    {
        int c_l = tid & 63;
        for (int tt = tid >> 6; tt < 64; tt += 4)
            g_y2[((size_t)nz * T_OUT + t0 + tt) * CCH + c0 + c_l] =
                __float2half_rn(stage[c_l][tt]);
    }
}

// ---------------- kernel 4: out GEMM: out[t][d] = sum_c y[t][c] W[d][c] ----------------
__global__ __launch_bounds__(256, 2) void k_out_mma(float* __restrict__ out) {
    extern __shared__ char smem[];
    const uint32_t sb = smem_u32(smem);
    const int tid = threadIdx.x, lane = tid & 31, wid = tid >> 5;
    const int wm = wid >> 2, wn = wid & 3;
    const int dt = blockIdx.x;
    const int t0 = blockIdx.y * 128;
    const int nz = blockIdx.z;

    const int row = tid >> 1;
    const int seg = (tid & 1) * 64;
    const uint32_t rowbase = row * 128;
    const uint32_t rxor = (row & 7) << 4;
    const __half* yrow_ptr = g_y2 + ((size_t)nz * T_OUT + t0 + row) * CCH;

    float acc[4][4][4];
#pragma unroll
    for (int i = 0; i < 4; i++)
#pragma unroll
        for (int j = 0; j < 4; j++)
#pragma unroll
            for (int q = 0; q < 4; q++) acc[i][j][q] = 0.0f;

#define OUT_ISSUE(cc, s) do { \
    const int kk = (cc) * 64 + seg / 2; \
    _Pragma("unroll") \
    for (int i = 0; i < 4; i++) \
        CP16(sb + (s) * 32768 + rowbase + ((seg + i * 16) ^ rxor), yrow_ptr + kk + i * 8); \
    const char* srcB = (const char*)(g_Bw + (size_t)(dt * 6 + (cc)) * 1024) + tid * 16; \
    uint32_t dB = sb + (s) * 32768 + 16384 + tid * 16; \
    _Pragma("unroll") \
    for (int i = 0; i < 4; i++) CP16(dB + i * 4096, srcB + i * 4096); \
} while (0)

    OUT_ISSUE(0, 0); CP_COMMIT();
    OUT_ISSUE(1, 1); CP_COMMIT();

    for (int c = 0; c < 6; c++) {
        CP_WAIT1();
        __syncthreads();
        if (c + 2 < 6) OUT_ISSUE(c + 2, (c + 2) % 3);
        CP_COMMIT();
        gemm16(sb, c % 3, wm, wn, lane, acc, 4);
    }

    // epilogue: out[(nz*T + t)*384 + d]
    const int tb = t0 + wm * 64;
    const int db = dt * 128 + wn * 32;
#pragma unroll
    for (int mf = 0; mf < 4; mf++) {
        int t = tb + mf * 16 + (lane >> 2);
        float* ob0 = out + ((size_t)nz * T_OUT + t) * CCH;
        float* ob1 = out + ((size_t)nz * T_OUT + t + 8) * CCH;
#pragma unroll
        for (int nf = 0; nf < 4; nf++) {
            int d = db + nf * 8 + (lane & 3) * 2;
            *(float2*)(ob0 + d) = make_float2(acc[mf][nf][0], acc[mf][nf][1]);
            *(float2*)(ob1 + d) = make_float2(acc[mf][nf][2], acc[mf][nf][3]);
        }
    }
#undef OUT_ISSUE
}

// ---------------------------------------------------------------------------
extern "C" void kernel_launch(void* const* d_in, const int* in_sizes, int n_in,
                              void* d_out, int out_size) {
    const float* noise = (const float*)d_in[0];   // [768, 65656]
    const float* sstd  = (const float*)d_in[1];   // [384]
    const float* vt    = (const float*)d_in[2];   // [384, 384]
    const float* H     = (const float*)d_in[3];   // [257]
    float* out = (float*)d_out;                   // [2, 65536, 384]

    cudaFuncSetAttribute(k_conv_mma, cudaFuncAttributeMaxDynamicSharedMemorySize, 98304);
    cudaFuncSetAttribute(k_out_mma,  cudaFuncAttributeMaxDynamicSharedMemorySize, 98304);

    k_irfft<<<1, 512>>>(H);
    k_build_Bc<<<dim3(4, 7), 256>>>();
    k_build_W<<<dim3(3, 6), 256>>>(vt, sstd);
    k_trunc_noise<<<(NROWS * T_PADDED) / 1024, 256>>>(noise);
    k_conv_mma<<<dim3(NCOLS / 128, 4), 256, 98304>>>();
    k_combineT<<<dim3(T_OUT / 64, CCH / 64, 2), 256>>>();
    k_out_mma<<<dim3(CCH / 128, T_OUT / 128, 2), 256, 98304>>>(out);
}

// round 9
// speedup vs baseline: 3.1709x; 1.1320x over previous
#include <cuda_runtime.h>
#include <cuda_fp16.h>
#include <cstdint>
#include <cstring>

// Problem constants
#define T_PADDED 65656
#define T_OUT    65536
#define NROWS    768
#define CCH      384
#define NB       168
#define HOP      392
#define OVL      120
#define NCOLS    (NROWS * NB)   // 129024

#define SWZ(x) ((x) ^ (((x) >> 3) & 0x70))

// ---------------- device globals (allocation-free rule) ----------------
__device__ float  g_h[512];
__device__ uint4  g_Bc[4 * 7 * 1024];              // circulant fp16 tiles [jt][kc], 16KB, SW128
__device__ uint4  g_Bw[3 * 6 * 1024];              // W fp16 tiles [dt][kc]
__device__ __half g_nh[(size_t)NROWS * T_PADDED];  // noise fp16 (rn)
__device__ __half g_C[(size_t)NB * 512 * NROWS];   // fp16 [b][j][r]

// ---------------- helpers ----------------
__device__ __forceinline__ uint32_t smem_u32(const void* p) {
    uint32_t a;
    asm("{ .reg .u64 t; cvta.to.shared.u64 t, %1; cvt.u32.u64 %0, t; }" : "=r"(a) : "l"(p));
    return a;
}
__device__ __forceinline__ void ldm4(uint32_t addr, uint32_t* r) {
    asm volatile("ldmatrix.sync.aligned.m8n8.x4.shared.b16 {%0,%1,%2,%3}, [%4];"
                 : "=r"(r[0]), "=r"(r[1]), "=r"(r[2]), "=r"(r[3]) : "r"(addr));
}
__device__ __forceinline__ void mma16816(float* c, const uint32_t* a, const uint32_t* b) {
    asm volatile("mma.sync.aligned.m16n8k16.row.col.f32.f16.f16.f32 "
                 "{%0,%1,%2,%3},{%4,%5,%6,%7},{%8,%9},{%0,%1,%2,%3};"
                 : "+f"(c[0]), "+f"(c[1]), "+f"(c[2]), "+f"(c[3])
                 : "r"(a[0]), "r"(a[1]), "r"(a[2]), "r"(a[3]), "r"(b[0]), "r"(b[1]));
}
__device__ __forceinline__ unsigned hadd2u(unsigned a, unsigned b) {
    __half2 x, y; memcpy(&x, &a, 4); memcpy(&y, &b, 4);
    __half2 z = __hadd2(x, y);
    unsigned u; memcpy(&u, &z, 4); return u;
}
#define CP16(s, g)     asm volatile("cp.async.cg.shared.global [%0], [%1], 16;" :: "r"(s), "l"(g))
#define CPZ(s, g, sz)  asm volatile("cp.async.cg.shared.global [%0], [%1], 16, %2;" :: "r"(s), "l"(g), "r"(sz))
#define CP_COMMIT()    asm volatile("cp.async.commit_group;" ::: "memory")
#define CP_WAIT1()     asm volatile("cp.async.wait_group 1;" ::: "memory")

// ---------------- kernel 1: h = irfft(H, 512) ----------------
__global__ void k_irfft(const float* __restrict__ H) {
    int j = threadIdx.x;
    float acc = H[0] + ((j & 1) ? -H[256] : H[256]);
    const float w = 6.283185307179586476f / 512.0f;
    for (int m = 1; m < 256; m++) {
        int ph = (m * j) & 511;
        acc += 2.0f * H[m] * cosf(w * (float)ph);
    }
    g_h[j] = acc * (1.0f / 512.0f);
}

// ---------------- kernel 1b: circulant tiles [j][k] fp16, SW128 ----------------
__global__ void k_build_Bc() {
    __shared__ float sh[512];
    int jt = blockIdx.x, kc = blockIdx.y;
    int tid = threadIdx.x;
    sh[tid] = g_h[tid]; sh[tid + 256] = g_h[tid + 256];
    __syncthreads();
    char* dst = (char*)g_Bc + (size_t)(jt * 7 + kc) * 16384;
    for (int e = tid; e < 8192; e += 256) {
        int jl = e >> 6, kl = e & 63;
        int k = kc * 64 + kl;
        float v = (k < HOP) ? sh[(jt * 128 + jl - k) & 511] : 0.0f;
        *(__half*)(dst + SWZ(jl * 128 + kl * 2)) = __float2half_rn(v);
    }
}

// ---------------- kernel 1c: W tiles [d][c] = std[c]*vt[c][d], fp16, SW128 ----------------
__global__ void k_build_W(const float* __restrict__ vt, const float* __restrict__ sstd) {
    int dt = blockIdx.x, kc = blockIdx.y;
    int tid = threadIdx.x;
    char* dst = (char*)g_Bw + (size_t)(dt * 6 + kc) * 16384;
    for (int e = tid; e < 8192; e += 256) {
        int kl = e >> 7, dl = e & 127;
        int c = kc * 64 + kl, d = dt * 128 + dl;
        float v = sstd[c] * vt[c * CCH + d];
        *(__half*)(dst + SWZ(dl * 128 + kl * 2)) = __float2half_rn(v);
    }
}

// ---------------- kernel 1d: noise -> fp16 plane ----------------
__global__ void k_trunc_noise(const float* __restrict__ noise) {
    size_t i = ((size_t)blockIdx.x * 256 + threadIdx.x) * 4;
    float4 v = *(const float4*)(noise + i);
    *(__half2*)(g_nh + i)     = __halves2half2(__float2half_rn(v.x), __float2half_rn(v.y));
    *(__half2*)(g_nh + i + 2) = __halves2half2(__float2half_rn(v.z), __float2half_rn(v.w));
}

// ============================================================================
// fp16 warp-MMA engine. Stage s at s*32768: A @+0 (128x128B, SW128), B @+16384.
// 8 warps: wm = wid>>2 (2) x wn = wid&3 (4); warp tile 64m x 32n.
// ============================================================================
__device__ __forceinline__ void gemm16(uint32_t sb, int s, int wm, int wn,
                                       int lane, float acc[4][4][4], int nks) {
    const uint32_t sx = (lane & 7) << 4;
    const int kA_l = (lane & 16) >> 1;
    const int kB_l = lane & 8;
    const int mrow = lane & 15;
    const int nrow = (lane & 7) + ((lane & 16) >> 1);
    const uint32_t aBase = sb + s * 32768 + (wm * 64 + mrow) * 128;
    const uint32_t bBase = sb + s * 32768 + 16384 + (wn * 32 + nrow) * 128;

#pragma unroll
    for (int ks = 0; ks < 4; ks++) {
        if (ks >= nks) break;
        const uint32_t ka = ((uint32_t)(ks * 16 + kA_l) * 2) ^ sx;
        const uint32_t kb = ((uint32_t)(ks * 16 + kB_l) * 2) ^ sx;
        uint32_t bh[4][2];
#pragma unroll
        for (int p = 0; p < 2; p++) {
            uint32_t r[4];
            ldm4(bBase + p * 2048 + kb, r);
            bh[2 * p][0] = r[0]; bh[2 * p][1] = r[1];
            bh[2 * p + 1][0] = r[2]; bh[2 * p + 1][1] = r[3];
        }
#pragma unroll
        for (int mf = 0; mf < 4; mf++) {
            uint32_t ah[4];
            ldm4(aBase + mf * 2048 + ka, ah);
#pragma unroll
            for (int nf = 0; nf < 4; nf++)
                mma16816(acc[mf][nf], ah, bh[nf]);
        }
    }
}

// ---------------- kernel 2: conv GEMM ----------------
// D[r][j] for block b: m = r (A = noise fp16), n = j (B = circulant tiles).
// Grid (jt, b*6+rt): jt fastest so co-resident CTAs share noise chunks in L2.
// Epilogue transposes through smem -> g_C[b][j][r] (r contiguous).
__global__ __launch_bounds__(256, 2) void k_conv_mma() {
    extern __shared__ char smem[];
    const uint32_t sb = smem_u32(smem);
    const int tid = threadIdx.x, lane = tid & 31, wid = tid >> 5;
    const int wm = wid >> 2, wn = wid & 3;
    const int jt = blockIdx.x;
    const int b  = blockIdx.y / 6;
    const int rt = blockIdx.y % 6;

    const int row = tid >> 1;
    const int seg = (tid & 1) * 64;       // byte offset in row
    const uint32_t rowbase = row * 128;
    const uint32_t rxor = (row & 7) << 4;
    const __half* nrow_ptr = g_nh + (size_t)(rt * 128 + row) * T_PADDED + b * HOP;
    const int krel = T_PADDED - b * HOP;

    float acc[4][4][4];
#pragma unroll
    for (int i = 0; i < 4; i++)
#pragma unroll
        for (int j = 0; j < 4; j++)
#pragma unroll
            for (int q = 0; q < 4; q++) acc[i][j][q] = 0.0f;

#define CONV_ISSUE(cc, s) do { \
    const int kk = (cc) * 64 + seg / 2; \
    _Pragma("unroll") \
    for (int i = 0; i < 4; i++) { \
        unsigned sz = (kk + i * 8 < krel) ? 16u : 0u; \
        CPZ(sb + (s) * 32768 + rowbase + ((seg + i * 16) ^ rxor), nrow_ptr + kk + i * 8, sz); \
    } \
    const char* srcB = (const char*)(g_Bc + (size_t)(jt * 7 + (cc)) * 1024) + tid * 16; \
    uint32_t dB = sb + (s) * 32768 + 16384 + tid * 16; \
    _Pragma("unroll") \
    for (int i = 0; i < 4; i++) CP16(dB + i * 4096, srcB + i * 4096); \
} while (0)

    CONV_ISSUE(0, 0); CP_COMMIT();
    CONV_ISSUE(1, 1); CP_COMMIT();

    for (int c = 0; c < 7; c++) {
        CP_WAIT1();                        // chunk c landed (this thread)
        __syncthreads();                   // visible to all; stage (c+2)%3 free
        if (c + 2 < 7) CONV_ISSUE(c + 2, (c + 2) % 3);
        CP_COMMIT();                       // unconditional: 1 group / iteration
        gemm16(sb, c % 3, wm, wn, lane, acc, (c == 6) ? 1 : 4);
    }

    // epilogue: transpose through smem, write g_C[b][j][r] (r contiguous)
    __syncthreads();
    {
        __half* st = (__half*)smem;       // [j][136] halves, 34816 B
#pragma unroll
        for (int mf = 0; mf < 4; mf++) {
            int m = wm * 64 + mf * 16 + (lane >> 2);
#pragma unroll
            for (int nf = 0; nf < 4; nf++) {
                int j = wn * 32 + nf * 8 + (lane & 3) * 2;
                st[j * 136 + m]           = __float2half_rn(acc[mf][nf][0]);
                st[(j + 1) * 136 + m]     = __float2half_rn(acc[mf][nf][1]);
                st[j * 136 + m + 8]       = __float2half_rn(acc[mf][nf][2]);
                st[(j + 1) * 136 + m + 8] = __float2half_rn(acc[mf][nf][3]);
            }
        }
        __syncthreads();
        const int jl = tid >> 1;
        const int sg = (tid & 1) * 64;    // halves
        const uint4* src = (const uint4*)(st + jl * 136 + sg);
        uint4* dst = (uint4*)(g_C + (size_t)(b * 512 + jt * 128 + jl) * 768 + rt * 128 + sg);
#pragma unroll
        for (int i = 0; i < 8; i++) dst[i] = src[i];
    }
#undef CONV_ISSUE
}

// ---------------- kernel 3: fused overlap-add + dewhiten GEMM ----------------
// out[nz][t][d] = sum_c y[t][c] * W[d][c],
//   y[t][c] = C[b2][j2][nz*384+c] (+ C[b2-1][j2+392][nz*384+c] if j2<120)
// m = t (A via LDG + hadd2 + STS), n = d (B = W tiles via cp.async).
__global__ __launch_bounds__(256, 2) void k_out_mma(float* __restrict__ out) {
    extern __shared__ char smem[];
    const uint32_t sb = smem_u32(smem);
    const int tid = threadIdx.x, lane = tid & 31, wid = tid >> 5;
    const int wm = wid >> 2, wn = wid & 3;
    const int dt = blockIdx.x;
    const int t0 = blockIdx.y * 128;
    const int nz = blockIdx.z;

    const int row = tid >> 1;
    const int segh = (tid & 1) * 32;      // half offset within chunk
    const int segB = (tid & 1) * 64;      // byte offset
    const uint32_t rowbase = row * 128;
    const uint32_t rxor = (row & 7) << 4;

    const int t = t0 + row;
    const int p = t + OVL;
    const int b2 = p / HOP;
    const int j2 = p - b2 * HOP;
    const __half* ybase = g_C + (size_t)(b2 * 512 + j2) * 768 + nz * CCH;
    const bool ov = (j2 < OVL);

    float acc[4][4][4];
#pragma unroll
    for (int i = 0; i < 4; i++)
#pragma unroll
        for (int j = 0; j < 4; j++)
#pragma unroll
            for (int q = 0; q < 4; q++) acc[i][j][q] = 0.0f;

    uint4 pf[4];

#define OUT_LDG(cc) do { \
    const int kk = (cc) * 64 + segh; \
    _Pragma("unroll") \
    for (int i = 0; i < 4; i++) { \
        uint4 v = *(const uint4*)(ybase + kk + i * 8); \
        if (ov) { \
            uint4 w = *(const uint4*)(ybase + kk + i * 8 - 92160); \
            v.x = hadd2u(v.x, w.x); v.y = hadd2u(v.y, w.y); \
            v.z = hadd2u(v.z, w.z); v.w = hadd2u(v.w, w.w); \
        } \
        pf[i] = v; \
    } \
} while (0)
#define OUT_STS(s) do { \
    _Pragma("unroll") \
    for (int i = 0; i < 4; i++) \
        *(uint4*)(smem + (s) * 32768 + rowbase + ((segB + i * 16) ^ rxor)) = pf[i]; \
} while (0)
#define OUT_CPB(cc, s) do { \
    const char* srcB = (const char*)(g_Bw + (size_t)(dt * 6 + (cc)) * 1024) + tid * 16; \
    uint32_t dB = sb + (s) * 32768 + 16384 + tid * 16; \
    _Pragma("unroll") \
    for (int i = 0; i < 4; i++) CP16(dB + i * 4096, srcB + i * 4096); \
} while (0)

    OUT_LDG(0); OUT_STS(0);
    OUT_LDG(1); OUT_STS(1);
    OUT_CPB(0, 0); CP_COMMIT();
    OUT_CPB(1, 1); CP_COMMIT();
    OUT_LDG(2);

    for (int c = 0; c < 6; c++) {
        CP_WAIT1();                        // B(c) landed (this thread)
        __syncthreads();                   // all copies + prior STS visible
        gemm16(sb, c & 1, wm, wn, lane, acc, 4);
        __syncthreads();                   // stage c&1 consumed by all warps
        if (c + 2 < 6) {
            OUT_CPB(c + 2, c & 1);
            OUT_STS(c & 1);                // pf holds chunk c+2
            if (c + 3 < 6) OUT_LDG(c + 3);
        }
        CP_COMMIT();                       // unconditional: 1 group / iteration
    }

    // epilogue: out[(nz*T + t)*384 + d]
    const int tb = t0 + wm * 64;
    const int db = dt * 128 + wn * 32;
#pragma unroll
    for (int mf = 0; mf < 4; mf++) {
        int tt = tb + mf * 16 + (lane >> 2);
        float* ob0 = out + ((size_t)nz * T_OUT + tt) * CCH;
        float* ob1 = out + ((size_t)nz * T_OUT + tt + 8) * CCH;
#pragma unroll
        for (int nf = 0; nf < 4; nf++) {
            int d = db + nf * 8 + (lane & 3) * 2;
            *(float2*)(ob0 + d) = make_float2(acc[mf][nf][0], acc[mf][nf][1]);
            *(float2*)(ob1 + d) = make_float2(acc[mf][nf][2], acc[mf][nf][3]);
        }
    }
#undef OUT_LDG
#undef OUT_STS
#undef OUT_CPB
}

// ---------------------------------------------------------------------------
extern "C" void kernel_launch(void* const* d_in, const int* in_sizes, int n_in,
                              void* d_out, int out_size) {
    const float* noise = (const float*)d_in[0];   // [768, 65656]
    const float* sstd  = (const float*)d_in[1];   // [384]
    const float* vt    = (const float*)d_in[2];   // [384, 384]
    const float* H     = (const float*)d_in[3];   // [257]
    float* out = (float*)d_out;                   // [2, 65536, 384]

    cudaFuncSetAttribute(k_conv_mma, cudaFuncAttributeMaxDynamicSharedMemorySize, 98304);
    cudaFuncSetAttribute(k_out_mma,  cudaFuncAttributeMaxDynamicSharedMemorySize, 65536);

    k_irfft<<<1, 512>>>(H);
    k_build_Bc<<<dim3(4, 7), 256>>>();
    k_build_W<<<dim3(3, 6), 256>>>(vt, sstd);
    k_trunc_noise<<<(NROWS * T_PADDED) / 1024, 256>>>(noise);
    k_conv_mma<<<dim3(4, NB * 6), 256, 98304>>>();
    k_out_mma<<<dim3(CCH / 128, T_OUT / 128, 2), 256, 65536>>>(out);
}

// round 10
// speedup vs baseline: 3.2649x; 1.0296x over previous
#include <cuda_runtime.h>
#include <cuda_fp16.h>
#include <cstdint>
#include <cstring>

// Problem constants
#define T_PADDED 65656
#define T_OUT    65536
#define NROWS    768
#define CCH      384
#define NB       168
#define HOP      392
#define OVL      120
#define NCOLS    (NROWS * NB)   // 129024

#define SWZ(x) ((x) ^ (((x) >> 3) & 0x70))

// ---------------- device globals (allocation-free rule) ----------------
__device__ float  g_h[512];
__device__ uint4  g_Bc[4 * 7 * 1024];              // circulant fp16 tiles [jt][kc], 16KB, SW128
__device__ uint4  g_Bw[3 * 6 * 1024];              // W fp16 tiles [dt][kc]
__device__ __half g_nh[(size_t)NROWS * T_PADDED];  // noise fp16 (rn)
__device__ __half g_C[(size_t)NB * 512 * NROWS];   // fp16 [b][j][r]

// ---------------- helpers ----------------
__device__ __forceinline__ uint32_t smem_u32(const void* p) {
    uint32_t a;
    asm("{ .reg .u64 t; cvta.to.shared.u64 t, %1; cvt.u32.u64 %0, t; }" : "=r"(a) : "l"(p));
    return a;
}
__device__ __forceinline__ void ldm4(uint32_t addr, uint32_t* r) {
    asm volatile("ldmatrix.sync.aligned.m8n8.x4.shared.b16 {%0,%1,%2,%3}, [%4];"
                 : "=r"(r[0]), "=r"(r[1]), "=r"(r[2]), "=r"(r[3]) : "r"(addr));
}
__device__ __forceinline__ void mma16816(float* c, const uint32_t* a, const uint32_t* b) {
    asm volatile("mma.sync.aligned.m16n8k16.row.col.f32.f16.f16.f32 "
                 "{%0,%1,%2,%3},{%4,%5,%6,%7},{%8,%9},{%0,%1,%2,%3};"
                 : "+f"(c[0]), "+f"(c[1]), "+f"(c[2]), "+f"(c[3])
                 : "r"(a[0]), "r"(a[1]), "r"(a[2]), "r"(a[3]), "r"(b[0]), "r"(b[1]));
}
__device__ __forceinline__ unsigned hadd2u(unsigned a, unsigned b) {
    __half2 x, y; memcpy(&x, &a, 4); memcpy(&y, &b, 4);
    __half2 z = __hadd2(x, y);
    unsigned u; memcpy(&u, &z, 4); return u;
}
#define CP16(s, g)     asm volatile("cp.async.cg.shared.global [%0], [%1], 16;" :: "r"(s), "l"(g))
#define CPZ(s, g, sz)  asm volatile("cp.async.cg.shared.global [%0], [%1], 16, %2;" :: "r"(s), "l"(g), "r"(sz))
#define CP_COMMIT()    asm volatile("cp.async.commit_group;" ::: "memory")
#define CP_WAIT1()     asm volatile("cp.async.wait_group 1;" ::: "memory")

// ---------------- kernel 1: h = irfft(H, 512) ----------------
__global__ void k_irfft(const float* __restrict__ H) {
    int j = threadIdx.x;
    float acc = H[0] + ((j & 1) ? -H[256] : H[256]);
    const float w = 6.283185307179586476f / 512.0f;
    for (int m = 1; m < 256; m++) {
        int ph = (m * j) & 511;
        acc += 2.0f * H[m] * cosf(w * (float)ph);
    }
    g_h[j] = acc * (1.0f / 512.0f);
}

// ---------------- kernel 1b: circulant tiles [j][k] fp16, SW128 ----------------
__global__ void k_build_Bc() {
    __shared__ float sh[512];
    int jt = blockIdx.x, kc = blockIdx.y;
    int tid = threadIdx.x;
    sh[tid] = g_h[tid]; sh[tid + 256] = g_h[tid + 256];
    __syncthreads();
    char* dst = (char*)g_Bc + (size_t)(jt * 7 + kc) * 16384;
    for (int e = tid; e < 8192; e += 256) {
        int jl = e >> 6, kl = e & 63;
        int k = kc * 64 + kl;
        float v = (k < HOP) ? sh[(jt * 128 + jl - k) & 511] : 0.0f;
        *(__half*)(dst + SWZ(jl * 128 + kl * 2)) = __float2half_rn(v);
    }
}

// ---------------- kernel 1c: W tiles [d][c] = std[c]*vt[c][d], fp16, SW128 ----------------
__global__ void k_build_W(const float* __restrict__ vt, const float* __restrict__ sstd) {
    int dt = blockIdx.x, kc = blockIdx.y;
    int tid = threadIdx.x;
    char* dst = (char*)g_Bw + (size_t)(dt * 6 + kc) * 16384;
    for (int e = tid; e < 8192; e += 256) {
        int kl = e >> 7, dl = e & 127;
        int c = kc * 64 + kl, d = dt * 128 + dl;
        float v = sstd[c] * vt[c * CCH + d];
        *(__half*)(dst + SWZ(dl * 128 + kl * 2)) = __float2half_rn(v);
    }
}

// ---------------- kernel 1d: noise -> fp16 plane ----------------
__global__ void k_trunc_noise(const float* __restrict__ noise) {
    size_t i = ((size_t)blockIdx.x * 256 + threadIdx.x) * 4;
    float4 v = *(const float4*)(noise + i);
    *(__half2*)(g_nh + i)     = __halves2half2(__float2half_rn(v.x), __float2half_rn(v.y));
    *(__half2*)(g_nh + i + 2) = __halves2half2(__float2half_rn(v.z), __float2half_rn(v.w));
}

// ============================================================================
// fp16 warp-MMA engine. Stage s at s*32768: A @+0 (128x128B, SW128), B @+16384.
// 8 warps: wm = wid>>2 (2) x wn = wid&3 (4); warp tile 64m x 32n.
// Templated kstep range so copy-issue can be interleaved between halves.
// ============================================================================
template <int KS0, int KS1>
__device__ __forceinline__ void gemm16(uint32_t sb, int s, int wm, int wn,
                                       int lane, float acc[4][4][4]) {
    const uint32_t sx = (lane & 7) << 4;
    const int kA_l = (lane & 16) >> 1;
    const int kB_l = lane & 8;
    const int mrow = lane & 15;
    const int nrow = (lane & 7) + ((lane & 16) >> 1);
    const uint32_t aBase = sb + s * 32768 + (wm * 64 + mrow) * 128;
    const uint32_t bBase = sb + s * 32768 + 16384 + (wn * 32 + nrow) * 128;

#pragma unroll
    for (int ks = KS0; ks < KS1; ks++) {
        const uint32_t ka = ((uint32_t)(ks * 16 + kA_l) * 2) ^ sx;
        const uint32_t kb = ((uint32_t)(ks * 16 + kB_l) * 2) ^ sx;
        uint32_t bh[4][2];
#pragma unroll
        for (int p = 0; p < 2; p++) {
            uint32_t r[4];
            ldm4(bBase + p * 2048 + kb, r);
            bh[2 * p][0] = r[0]; bh[2 * p][1] = r[1];
            bh[2 * p + 1][0] = r[2]; bh[2 * p + 1][1] = r[3];
        }
#pragma unroll
        for (int mf = 0; mf < 4; mf++) {
            uint32_t ah[4];
            ldm4(aBase + mf * 2048 + ka, ah);
#pragma unroll
            for (int nf = 0; nf < 4; nf++)
                mma16816(acc[mf][nf], ah, bh[nf]);
        }
    }
}

// ---------------- kernel 2: conv GEMM ----------------
// D[r][j] for block b: m = r (A = noise fp16), n = j (B = circulant tiles).
// Grid (jt, b*6+rt): jt fastest so co-resident CTAs share noise chunks in L2.
// 3-stage cp.async pipeline, single sync per chunk, copy-issue interleaved.
// Epilogue transposes through smem -> g_C[b][j][r] (r contiguous).
__global__ __launch_bounds__(256, 2) void k_conv_mma() {
    extern __shared__ char smem[];
    const uint32_t sb = smem_u32(smem);
    const int tid = threadIdx.x, lane = tid & 31, wid = tid >> 5;
    const int wm = wid >> 2, wn = wid & 3;
    const int jt = blockIdx.x;
    const int b  = blockIdx.y / 6;
    const int rt = blockIdx.y % 6;

    const int row = tid >> 1;
    const int seg = (tid & 1) * 64;       // byte offset in row
    const uint32_t rowbase = row * 128;
    const uint32_t rxor = (row & 7) << 4;
    const __half* nrow_ptr = g_nh + (size_t)(rt * 128 + row) * T_PADDED + b * HOP;
    const int krel = T_PADDED - b * HOP;

    float acc[4][4][4];
#pragma unroll
    for (int i = 0; i < 4; i++)
#pragma unroll
        for (int j = 0; j < 4; j++)
#pragma unroll
            for (int q = 0; q < 4; q++) acc[i][j][q] = 0.0f;

#define CONV_ISSUE(cc, s) do { \
    const int kk = (cc) * 64 + seg / 2; \
    _Pragma("unroll") \
    for (int i = 0; i < 4; i++) { \
        unsigned sz = (kk + i * 8 < krel) ? 16u : 0u; \
        CPZ(sb + (s) * 32768 + rowbase + ((seg + i * 16) ^ rxor), nrow_ptr + kk + i * 8, sz); \
    } \
    const char* srcB = (const char*)(g_Bc + (size_t)(jt * 7 + (cc)) * 1024) + tid * 16; \
    uint32_t dB = sb + (s) * 32768 + 16384 + tid * 16; \
    _Pragma("unroll") \
    for (int i = 0; i < 4; i++) CP16(dB + i * 4096, srcB + i * 4096); \
} while (0)

    CONV_ISSUE(0, 0); CP_COMMIT();
    CONV_ISSUE(1, 1); CP_COMMIT();

#pragma unroll 1
    for (int c = 0; c < 6; c++) {
        CP_WAIT1();                        // chunk c landed (this thread)
        __syncthreads();                   // visible to all; stage (c+2)%3 free
        gemm16<0, 2>(sb, c % 3, wm, wn, lane, acc);
        CONV_ISSUE(c + 2, (c + 2) % 3);    // c+2 <= 7? c<6 -> c+2<8; guard:
        CP_COMMIT();
        gemm16<2, 4>(sb, c % 3, wm, wn, lane, acc);
    }
    // tail chunk c = 6 (1 kstep; K=392 ends at 6*64+8..)
    CP_WAIT1();
    __syncthreads();
    gemm16<0, 1>(sb, 0 /* 6%3 */, wm, wn, lane, acc);

    // epilogue: transpose through smem, write g_C[b][j][r] (r contiguous)
    __syncthreads();
    {
        __half* st = (__half*)smem;       // [j][136] halves, 34816 B
#pragma unroll
        for (int mf = 0; mf < 4; mf++) {
            int m = wm * 64 + mf * 16 + (lane >> 2);
#pragma unroll
            for (int nf = 0; nf < 4; nf++) {
                int j = wn * 32 + nf * 8 + (lane & 3) * 2;
                st[j * 136 + m]           = __float2half_rn(acc[mf][nf][0]);
                st[(j + 1) * 136 + m]     = __float2half_rn(acc[mf][nf][1]);
                st[j * 136 + m + 8]       = __float2half_rn(acc[mf][nf][2]);
                st[(j + 1) * 136 + m + 8] = __float2half_rn(acc[mf][nf][3]);
            }
        }
        __syncthreads();
        const int jl = tid >> 1;
        const int sg = (tid & 1) * 64;    // halves
        const uint4* src = (const uint4*)(st + jl * 136 + sg);
        uint4* dst = (uint4*)(g_C + (size_t)(b * 512 + jt * 128 + jl) * 768 + rt * 128 + sg);
#pragma unroll
        for (int i = 0; i < 8; i++) dst[i] = src[i];
    }
#undef CONV_ISSUE
}

// ---------------- kernel 3: fused overlap-add + dewhiten GEMM ----------------
// out[nz][t][d] = sum_c y[t][c] * W[d][c],
//   y[t][c] = C[b2][j2][nz*384+c] (+ C[b2-1][j2+392][nz*384+c] if j2<120)
// m = t (A via LDG + hadd2 + STS), n = d (B = W tiles via cp.async).
// 3-stage, single sync per chunk, copy-issue interleaved between gemm halves.
__global__ __launch_bounds__(256, 2) void k_out_mma(float* __restrict__ out) {
    extern __shared__ char smem[];
    const uint32_t sb = smem_u32(smem);
    const int tid = threadIdx.x, lane = tid & 31, wid = tid >> 5;
    const int wm = wid >> 2, wn = wid & 3;
    const int dt = blockIdx.x;
    const int t0 = blockIdx.y * 128;
    const int nz = blockIdx.z;

    const int row = tid >> 1;
    const int segh = (tid & 1) * 32;      // half offset within chunk
    const int segB = (tid & 1) * 64;      // byte offset
    const uint32_t rowbase = row * 128;
    const uint32_t rxor = (row & 7) << 4;

    const int t = t0 + row;
    const int p = t + OVL;
    const int b2 = p / HOP;
    const int j2 = p - b2 * HOP;
    const __half* ybase = g_C + (size_t)(b2 * 512 + j2) * 768 + nz * CCH;
    const bool ov = (j2 < OVL);

    float acc[4][4][4];
#pragma unroll
    for (int i = 0; i < 4; i++)
#pragma unroll
        for (int j = 0; j < 4; j++)
#pragma unroll
            for (int q = 0; q < 4; q++) acc[i][j][q] = 0.0f;

    uint4 pf[4];

#define OUT_LDG(cc) do { \
    const int kk = (cc) * 64 + segh; \
    _Pragma("unroll") \
    for (int i = 0; i < 4; i++) { \
        uint4 v = *(const uint4*)(ybase + kk + i * 8); \
        if (ov) { \
            uint4 w = *(const uint4*)(ybase + kk + i * 8 - 92160); \
            v.x = hadd2u(v.x, w.x); v.y = hadd2u(v.y, w.y); \
            v.z = hadd2u(v.z, w.z); v.w = hadd2u(v.w, w.w); \
        } \
        pf[i] = v; \
    } \
} while (0)
#define OUT_STS(s) do { \
    _Pragma("unroll") \
    for (int i = 0; i < 4; i++) \
        *(uint4*)(smem + (s) * 32768 + rowbase + ((segB + i * 16) ^ rxor)) = pf[i]; \
} while (0)
#define OUT_CPB(cc, s) do { \
    const char* srcB = (const char*)(g_Bw + (size_t)(dt * 6 + (cc)) * 1024) + tid * 16; \
    uint32_t dB = sb + (s) * 32768 + 16384 + tid * 16; \
    _Pragma("unroll") \
    for (int i = 0; i < 4; i++) CP16(dB + i * 4096, srcB + i * 4096); \
} while (0)

    // prologue: stages 0,1 filled; pf = chunk 2
    OUT_LDG(0); OUT_STS(0);
    OUT_LDG(1); OUT_STS(1);
    OUT_CPB(0, 0); CP_COMMIT();
    OUT_CPB(1, 1); CP_COMMIT();
    OUT_LDG(2);

#pragma unroll 1
    for (int c = 0; c < 6; c++) {
        CP_WAIT1();                        // B(c) landed (this thread)
        __syncthreads();                   // copies + STS(c) visible; stage (c+2)%3 free
        gemm16<0, 2>(sb, c % 3, wm, wn, lane, acc);
        if (c + 2 < 6) {
            OUT_CPB(c + 2, (c + 2) % 3);
            OUT_STS((c + 2) % 3);          // pf holds chunk c+2
        }
        CP_COMMIT();                       // unconditional: 1 group / iteration
        if (c + 3 < 6) OUT_LDG(c + 3);     // refill pf
        gemm16<2, 4>(sb, c % 3, wm, wn, lane, acc);
    }

    // epilogue: out[(nz*T + t)*384 + d]
    const int tb = t0 + wm * 64;
    const int db = dt * 128 + wn * 32;
#pragma unroll
    for (int mf = 0; mf < 4; mf++) {
        int tt = tb + mf * 16 + (lane >> 2);
        float* ob0 = out + ((size_t)nz * T_OUT + tt) * CCH;
        float* ob1 = out + ((size_t)nz * T_OUT + tt + 8) * CCH;
#pragma unroll
        for (int nf = 0; nf < 4; nf++) {
            int d = db + nf * 8 + (lane & 3) * 2;
            *(float2*)(ob0 + d) = make_float2(acc[mf][nf][0], acc[mf][nf][1]);
            *(float2*)(ob1 + d) = make_float2(acc[mf][nf][2], acc[mf][nf][3]);
        }
    }
#undef OUT_LDG
#undef OUT_STS
#undef OUT_CPB
}

// ---------------------------------------------------------------------------
extern "C" void kernel_launch(void* const* d_in, const int* in_sizes, int n_in,
                              void* d_out, int out_size) {
    const float* noise = (const float*)d_in[0];   // [768, 65656]
    const float* sstd  = (const float*)d_in[1];   // [384]
    const float* vt    = (const float*)d_in[2];   // [384, 384]
    const float* H     = (const float*)d_in[3];   // [257]
    float* out = (float*)d_out;                   // [2, 65536, 384]

    cudaFuncSetAttribute(k_conv_mma, cudaFuncAttributeMaxDynamicSharedMemorySize, 98304);
    cudaFuncSetAttribute(k_out_mma,  cudaFuncAttributeMaxDynamicSharedMemorySize, 98304);

    k_irfft<<<1, 512>>>(H);
    k_build_Bc<<<dim3(4, 7), 256>>>();
    k_build_W<<<dim3(3, 6), 256>>>(vt, sstd);
    k_trunc_noise<<<(NROWS * T_PADDED) / 1024, 256>>>(noise);
    k_conv_mma<<<dim3(4, NB * 6), 256, 98304>>>();
    k_out_mma<<<dim3(CCH / 128, T_OUT / 128, 2), 256, 98304>>>(out);
}